// round 5
// baseline (speedup 1.0000x reference)
#include <cuda_runtime.h>
#include <math.h>

#define BB 64
#define TT 512
#define DD 512
#define II 1024
#define GG 2048                 // 4*D
#define BT (BB*TT)              // 32768

// ---------------- device scratch (static: allocation-free at run time) -------
__device__ float g_xw1[BT * GG];   // x  @ W1 + b1   [B,T,4D]
__device__ float g_xwf[BT * GG];   // h1 @ Wf + bf
__device__ float g_xwb[BT * GG];   // h1 @ Wb + bb
__device__ float g_h1 [BT * DD];   // layer-1 hidden sequence [B,T,D]
__device__ float g_hf [BT * DD];   // forward hidden sequence
__device__ float g_hb [BT * DD];   // backward hidden sequence (time-indexed)

// ---------------- software grid barrier (persistent kernels) ----------------
__device__ unsigned g_cnt = 0;
__device__ unsigned g_gen = 0;

__device__ __forceinline__ void grid_barrier(unsigned nb) {
    __threadfence();            // release: make h[t]/c writes visible device-wide
    __syncthreads();
    if (threadIdx.x == 0) {
        unsigned gen = *((volatile unsigned*)&g_gen);
        unsigned a = atomicAdd(&g_cnt, 1);
        if (a == nb - 1) {
            g_cnt = 0;          // safe: nobody re-arrives until gen bumps
            __threadfence();
            atomicAdd(&g_gen, 1);
        } else {
            while (*((volatile unsigned*)&g_gen) == gen) { __nanosleep(32); }
        }
        __threadfence();        // acquire
    }
    __syncthreads();
}

// ---------------- fp32 tiled GEMM:  C[BT,GG] = A[BT,K] @ W[K,GG] + bias -----
// 128x128 tile, BK=8, 256 threads, 8x8 microtile.
__global__ void __launch_bounds__(256) k_sgemm_bias(
    const float* __restrict__ A, const float* __restrict__ W,
    const float* __restrict__ bias, float* __restrict__ C, int K)
{
    __shared__ float As[8][128];
    __shared__ float Bs[8][128];

    const int tid  = threadIdx.x;
    const int row0 = blockIdx.y * 128;
    const int col0 = blockIdx.x * 128;
    const int tx   = tid & 15;
    const int ty   = tid >> 4;

    const int arow = tid >> 1;
    const int acol = (tid & 1) << 2;
    const int brow = tid >> 5;
    const int bcol = (tid & 31) << 2;

    const float* Aptr = A + (size_t)(row0 + arow) * K + acol;
    const float* Wptr = W + (size_t)brow * GG + col0 + bcol;

    float acc[8][8];
#pragma unroll
    for (int i = 0; i < 8; i++)
#pragma unroll
        for (int j = 0; j < 8; j++) acc[i][j] = 0.f;

    for (int k0 = 0; k0 < K; k0 += 8) {
        float4 av = *(const float4*)(Aptr + k0);
        float4 bv = *(const float4*)(Wptr + (size_t)k0 * GG);
        __syncthreads();
        As[acol + 0][arow] = av.x;
        As[acol + 1][arow] = av.y;
        As[acol + 2][arow] = av.z;
        As[acol + 3][arow] = av.w;
        *(float4*)&Bs[brow][bcol] = bv;
        __syncthreads();
#pragma unroll
        for (int k = 0; k < 8; k++) {
            float a[8], b[8];
            *(float4*)&a[0] = *(const float4*)&As[k][ty * 8];
            *(float4*)&a[4] = *(const float4*)&As[k][ty * 8 + 4];
            *(float4*)&b[0] = *(const float4*)&Bs[k][tx * 8];
            *(float4*)&b[4] = *(const float4*)&Bs[k][tx * 8 + 4];
#pragma unroll
            for (int i = 0; i < 8; i++)
#pragma unroll
                for (int j = 0; j < 8; j++)
                    acc[i][j] = fmaf(a[i], b[j], acc[i][j]);
        }
    }

    float bsv[8];
#pragma unroll
    for (int j = 0; j < 8; j++) bsv[j] = bias[col0 + tx * 8 + j];
#pragma unroll
    for (int i = 0; i < 8; i++) {
        size_t crow = (size_t)(row0 + ty * 8 + i);
        float4 v0, v1;
        v0.x = acc[i][0] + bsv[0]; v0.y = acc[i][1] + bsv[1];
        v0.z = acc[i][2] + bsv[2]; v0.w = acc[i][3] + bsv[3];
        v1.x = acc[i][4] + bsv[4]; v1.y = acc[i][5] + bsv[5];
        v1.z = acc[i][6] + bsv[6]; v1.w = acc[i][7] + bsv[7];
        *(float4*)&C[crow * GG + col0 + tx * 8]     = v0;
        *(float4*)&C[crow * GG + col0 + tx * 8 + 4] = v1;
    }
}

// ---------------- one LSTM timestep (device function) -----------------------
// Block = 4 units (16 gate-columns of U), all 64 batch rows.
// z[b, col] = xw[b, tout, col] + sum_k h_prev[b,k] * U[k,col], then gates.
// h_prev read from seq at timestep tprev (tprev < 0 => zero state).
// Cell state lives in a per-thread register (thread -> fixed (batch, unit)).
__device__ __forceinline__ void lstm_step(
    const float* __restrict__ xw, const float* __restrict__ U,
    float* __restrict__ seq, int tout, int tprev, int u0, float& c_reg,
    float (*Hs)[68], float (*Us)[16], float (*zbuf)[16])
{
    const int tid = threadIdx.x;
    const int b   = tid >> 2;         // compute row (batch)
    const int c0  = (tid & 3) * 4;    // first of 4 gate-cols (one gate)

    float acc0 = 0.f, acc1 = 0.f, acc2 = 0.f, acc3 = 0.f;

    if (tprev >= 0) {
        const int hb0 = tid >> 4;          // 0..15 (+16r rows)
        const int hk  = (tid & 15) << 2;   // k offset within chunk
        const int ukk = tid >> 2;          // 0..63
        const int ug  = tid & 3;           // gate

        float4 hv[4]; float4 uv;
#pragma unroll
        for (int r = 0; r < 4; r++)
            hv[r] = *(const float4*)&seq[((size_t)(hb0 + 16 * r) * TT + tprev) * DD + hk];
        uv = *(const float4*)&U[(size_t)ukk * GG + ug * DD + u0];

#pragma unroll
        for (int k0 = 0; k0 < DD; k0 += 64) {
            __syncthreads();
#pragma unroll
            for (int r = 0; r < 4; r++)
                *(float4*)&Hs[hb0 + 16 * r][hk] = hv[r];
            *(float4*)&Us[ukk][ug << 2] = uv;
            if (k0 + 64 < DD) {   // prefetch next chunk (overlaps with compute)
#pragma unroll
                for (int r = 0; r < 4; r++)
                    hv[r] = *(const float4*)&seq[((size_t)(hb0 + 16 * r) * TT + tprev) * DD + (k0 + 64) + hk];
                uv = *(const float4*)&U[(size_t)(k0 + 64 + ukk) * GG + ug * DD + u0];
            }
            __syncthreads();
#pragma unroll
            for (int k = 0; k < 64; k++) {
                float  a  = Hs[b][k];
                float4 u4 = *(const float4*)&Us[k][c0];
                acc0 = fmaf(a, u4.x, acc0);
                acc1 = fmaf(a, u4.y, acc1);
                acc2 = fmaf(a, u4.z, acc2);
                acc3 = fmaf(a, u4.w, acc3);
            }
        }
    }

    __syncthreads();
    {
        float4 z; z.x = acc0; z.y = acc1; z.z = acc2; z.w = acc3;
        *(float4*)&zbuf[b][c0] = z;
    }
    __syncthreads();

    // gate phase: thread -> (batch b2, unit du); same mapping every step
    {
        const int b2   = tid >> 2;
        const int du   = tid & 3;
        const int unit = u0 + du;
        const size_t row = (size_t)b2 * TT + tout;
        float zi = zbuf[b2][ 0 + du] + xw[row * GG + 0 * DD + unit];
        float zf = zbuf[b2][ 4 + du] + xw[row * GG + 1 * DD + unit];
        float zg = zbuf[b2][ 8 + du] + xw[row * GG + 2 * DD + unit];
        float zo = zbuf[b2][12 + du] + xw[row * GG + 3 * DD + unit];
        float si = 1.f / (1.f + __expf(-zi));
        float sf = 1.f / (1.f + __expf(-zf));
        float so = 1.f / (1.f + __expf(-zo));
        float gr = fmaxf(zg, 0.f);
        float cn = sf * c_reg + si * gr;
        c_reg = cn;
        seq[row * DD + unit] = so * fmaxf(cn, 0.f);
    }
}

// ---------------- persistent layer-1 recurrence (1 launch, 512 steps) -------
__global__ void __launch_bounds__(256) k_lstm_layer1(
    const float* __restrict__ xw, const float* __restrict__ U,
    float* __restrict__ seq)
{
    __shared__ float Hs[64][68];
    __shared__ float Us[64][16];
    __shared__ float zbuf[64][16];

    const int u0 = blockIdx.x * 4;
    float c_reg = 0.f;

    for (int t = 0; t < TT; t++) {
        lstm_step(xw, U, seq, t, t - 1, u0, c_reg, Hs, Us, zbuf);
        grid_barrier(gridDim.x);
    }
}

// ---------------- persistent fused forward+backward recurrence --------------
__global__ void __launch_bounds__(256) k_lstm_layer2(
    const float* __restrict__ xwf, const float* __restrict__ Uf,
    float* __restrict__ hf,
    const float* __restrict__ xwb, const float* __restrict__ Ub,
    float* __restrict__ hb)
{
    __shared__ float Hs[64][68];
    __shared__ float Us[64][16];
    __shared__ float zbuf[64][16];

    const int u0 = blockIdx.x * 4;
    float cF = 0.f, cB = 0.f;

    for (int s = 0; s < TT; s++) {
        lstm_step(xwf, Uf, hf, s, s - 1, u0, cF, Hs, Us, zbuf);
        lstm_step(xwb, Ub, hb, TT - 1 - s, (s == 0) ? -1 : TT - s, u0, cB,
                  Hs, Us, zbuf);
        grid_barrier(gridDim.x);
    }
}

// ---------------- LayerNorm(concat(hf,hb)) * gamma + beta + residual -------
__global__ void __launch_bounds__(256) k_ln_residual(
    const float* __restrict__ x, const float* __restrict__ gamma,
    const float* __restrict__ beta, const float* __restrict__ hf,
    const float* __restrict__ hb, float* __restrict__ out)
{
    const int bt  = blockIdx.x;           // b*T + t
    const int tid = threadIdx.x;
    const float* hfr = hf + (size_t)bt * DD;
    const float* hbr = hb + (size_t)bt * DD;

    float v[4];
    float s = 0.f;
#pragma unroll
    for (int r = 0; r < 4; r++) {
        int i = tid + r * 256;
        float val = (i < DD) ? hfr[i] : hbr[i - DD];
        v[r] = val; s += val;
    }

    __shared__ float rbuf[8];
    __shared__ float stat[2];
    const int lane = tid & 31, w = tid >> 5;
#pragma unroll
    for (int o = 16; o; o >>= 1) s += __shfl_xor_sync(0xffffffffu, s, o);
    if (lane == 0) rbuf[w] = s;
    __syncthreads();
    if (tid == 0) {
        float t = 0.f;
        for (int i = 0; i < 8; i++) t += rbuf[i];
        stat[0] = t * (1.f / 1024.f);
    }
    __syncthreads();
    const float mean = stat[0];

    float s2 = 0.f;
#pragma unroll
    for (int r = 0; r < 4; r++) { float d = v[r] - mean; s2 += d * d; }
#pragma unroll
    for (int o = 16; o; o >>= 1) s2 += __shfl_xor_sync(0xffffffffu, s2, o);
    if (lane == 0) rbuf[w] = s2;
    __syncthreads();
    if (tid == 0) {
        float t = 0.f;
        for (int i = 0; i < 8; i++) t += rbuf[i];
        stat[1] = rsqrtf(t * (1.f / 1024.f) + 1e-6f);
    }
    __syncthreads();
    const float rstd = stat[1];

    const float* xr  = x   + (size_t)bt * II;
    float*       otr = out + (size_t)bt * II;
#pragma unroll
    for (int r = 0; r < 4; r++) {
        int i = tid + r * 256;
        otr[i] = xr[i] + (v[r] - mean) * rstd * gamma[i] + beta[i];
    }
}

// ---------------- launcher ----------------------------------------------
extern "C" void kernel_launch(void* const* d_in, const int* in_sizes, int n_in,
                              void* d_out, int out_size)
{
    (void)in_sizes; (void)n_in; (void)out_size;
    const float* x     = (const float*)d_in[0];
    const float* W1    = (const float*)d_in[1];
    const float* U1    = (const float*)d_in[2];
    const float* b1    = (const float*)d_in[3];
    const float* Wf    = (const float*)d_in[4];
    const float* Uf    = (const float*)d_in[5];
    const float* bf    = (const float*)d_in[6];
    const float* Wb    = (const float*)d_in[7];
    const float* Ub    = (const float*)d_in[8];
    const float* bb    = (const float*)d_in[9];
    const float* gamma = (const float*)d_in[10];
    const float* beta  = (const float*)d_in[11];
    float* out = (float*)d_out;

    float *xw1, *xwf, *xwb, *h1, *hf, *hb;
    cudaGetSymbolAddress((void**)&xw1, g_xw1);
    cudaGetSymbolAddress((void**)&xwf, g_xwf);
    cudaGetSymbolAddress((void**)&xwb, g_xwb);
    cudaGetSymbolAddress((void**)&h1,  g_h1);
    cudaGetSymbolAddress((void**)&hf,  g_hf);
    cudaGetSymbolAddress((void**)&hb,  g_hb);

    dim3 ggrid(GG / 128, BT / 128);   // (16, 256)

    // layer 1 input projection: xw1 = x @ W1 + b1   (K = 1024)
    k_sgemm_bias<<<ggrid, 256>>>(x, W1, b1, xw1, II);

    // layer 1 recurrence: one persistent kernel, 512 steps, grid barrier/step
    k_lstm_layer1<<<DD / 4, 256>>>(xw1, U1, h1);

    // forward / backward input projections (K = 512)
    k_sgemm_bias<<<ggrid, 256>>>(h1, Wf, bf, xwf, DD);
    k_sgemm_bias<<<ggrid, 256>>>(h1, Wb, bb, xwb, DD);

    // fused forward + backward recurrence: one persistent kernel
    k_lstm_layer2<<<DD / 4, 256>>>(xwf, Uf, hf, xwb, Ub, hb);

    // layernorm + residual
    k_ln_residual<<<BT, 256>>>(x, gamma, beta, hf, hb, out);
}

// round 6
// speedup vs baseline: 2.7372x; 2.7372x over previous
#include <cuda_runtime.h>
#include <math.h>

#define BB 64
#define TT 512
#define DD 512
#define II 1024
#define GG 2048                 // 4*D
#define BT (BB*TT)              // 32768

// ---------------- device scratch (static: allocation-free at run time) ------
__device__ float g_xw1[BT * GG];   // x  @ W1 + b1   [B,T,4D]
__device__ float g_xwf[BT * GG];   // h1 @ Wf + bf
__device__ float g_xwb[BT * GG];   // h1 @ Wb + bb
__device__ float g_h1 [BT * DD];   // layer-1 hidden sequence [B,T,D]
__device__ float g_hf [BT * DD];   // forward hidden sequence
__device__ float g_hb [BT * DD];   // backward hidden sequence

// ---------------- software grid barrier (persistent kernels) ----------------
__device__ unsigned g_cnt = 0;
__device__ unsigned g_gen = 0;

__device__ __forceinline__ void grid_barrier(unsigned nb) {
    __threadfence();
    __syncthreads();
    if (threadIdx.x == 0) {
        unsigned gen = *((volatile unsigned*)&g_gen);
        unsigned a = atomicAdd(&g_cnt, 1);
        if (a == nb - 1) {
            g_cnt = 0;
            __threadfence();
            atomicAdd(&g_gen, 1);
        } else {
            while (*((volatile unsigned*)&g_gen) == gen) { __nanosleep(32); }
        }
        __threadfence();
    }
    __syncthreads();
}

// ---------------- tf32 helpers ----------------------------------------------
__device__ __forceinline__ unsigned f2tf(float f) {
    unsigned r; asm("cvt.rna.tf32.f32 %0, %1;" : "=r"(r) : "f"(f)); return r;
}

__device__ __forceinline__ void mma_tf32(float* d, const unsigned* a, const unsigned* b) {
    asm volatile("mma.sync.aligned.m16n8k8.row.col.f32.tf32.tf32.f32 "
        "{%0,%1,%2,%3}, {%4,%5,%6,%7}, {%8,%9}, {%0,%1,%2,%3};\n"
        : "+f"(d[0]), "+f"(d[1]), "+f"(d[2]), "+f"(d[3])
        : "r"(a[0]), "r"(a[1]), "r"(a[2]), "r"(a[3]), "r"(b[0]), "r"(b[1]));
}

// ---------------- tf32 MMA GEMM: C[BT,GG] = A[BT,K] @ W[K,GG] + bias --------
// 128x128 block tile, k-chunk 32, 8 warps (2m x 4n), warp tile 64x32.
__global__ void __launch_bounds__(256) k_mma_gemm(
    const float* __restrict__ A, const float* __restrict__ W,
    const float* __restrict__ bias, float* __restrict__ C, int K)
{
    __shared__ unsigned As[128][36];   // [m][k] pad 36 -> frag bank = 4g+t (free)
    __shared__ unsigned Bs[32][136];   // [k][n] pad 136 -> frag bank = 8t+g (free)

    const int tid  = threadIdx.x;
    const int warp = tid >> 5, lane = tid & 31;
    const int g    = lane >> 2, t = lane & 3;
    const int wm   = (warp >> 2) * 64;
    const int wn   = (warp & 3) * 32;
    const int row0 = blockIdx.y * 128, col0 = blockIdx.x * 128;

    const int a_m  = tid >> 3;         // + i*32
    const int a_k4 = (tid & 7) * 4;
    const int b_k  = tid >> 5;         // + i*8
    const int b_n4 = (tid & 31) * 4;

    float acc[4][4][4];
#pragma unroll
    for (int mi = 0; mi < 4; mi++)
#pragma unroll
        for (int ni = 0; ni < 4; ni++)
#pragma unroll
            for (int r = 0; r < 4; r++) acc[mi][ni][r] = 0.f;

    const float* Ap = A + (size_t)(row0 + a_m) * K + a_k4;
    const float* Wp = W + (size_t)b_k * GG + col0 + b_n4;

    float4 av[4], bv[4];
#pragma unroll
    for (int i = 0; i < 4; i++) av[i] = *(const float4*)(Ap + (size_t)(i * 32) * K);
#pragma unroll
    for (int i = 0; i < 4; i++) bv[i] = *(const float4*)(Wp + (size_t)(i * 8) * GG);

    for (int k0 = 0; k0 < K; k0 += 32) {
        __syncthreads();
#pragma unroll
        for (int i = 0; i < 4; i++) {
            uint4 u; u.x = f2tf(av[i].x); u.y = f2tf(av[i].y);
                     u.z = f2tf(av[i].z); u.w = f2tf(av[i].w);
            *(uint4*)&As[i * 32 + a_m][a_k4] = u;
        }
#pragma unroll
        for (int i = 0; i < 4; i++) {
            uint4 u; u.x = f2tf(bv[i].x); u.y = f2tf(bv[i].y);
                     u.z = f2tf(bv[i].z); u.w = f2tf(bv[i].w);
            *(uint4*)&Bs[i * 8 + b_k][b_n4] = u;
        }
        if (k0 + 32 < K) {
#pragma unroll
            for (int i = 0; i < 4; i++)
                av[i] = *(const float4*)(Ap + (size_t)(i * 32) * K + (k0 + 32));
#pragma unroll
            for (int i = 0; i < 4; i++)
                bv[i] = *(const float4*)(Wp + (size_t)(k0 + 32 + i * 8) * GG);
        }
        __syncthreads();

#pragma unroll
        for (int s = 0; s < 4; s++) {
            const int kk = s * 8;
            unsigned af[4][4];
#pragma unroll
            for (int mi = 0; mi < 4; mi++) {
                const int r = wm + mi * 16;
                af[mi][0] = As[r + g    ][kk + t];
                af[mi][1] = As[r + g + 8][kk + t];
                af[mi][2] = As[r + g    ][kk + t + 4];
                af[mi][3] = As[r + g + 8][kk + t + 4];
            }
            unsigned bf[4][2];
#pragma unroll
            for (int ni = 0; ni < 4; ni++) {
                bf[ni][0] = Bs[kk + t    ][wn + ni * 8 + g];
                bf[ni][1] = Bs[kk + t + 4][wn + ni * 8 + g];
            }
#pragma unroll
            for (int mi = 0; mi < 4; mi++)
#pragma unroll
                for (int ni = 0; ni < 4; ni++)
                    mma_tf32(acc[mi][ni], af[mi], bf[ni]);
        }
    }

    // epilogue: + bias, store
#pragma unroll
    for (int mi = 0; mi < 4; mi++) {
        const int r0 = row0 + wm + mi * 16 + g;
#pragma unroll
        for (int ni = 0; ni < 4; ni++) {
            const int cb = col0 + wn + ni * 8 + 2 * t;
            const float b0 = bias[cb], b1 = bias[cb + 1];
            float2 v0; v0.x = acc[mi][ni][0] + b0; v0.y = acc[mi][ni][1] + b1;
            float2 v1; v1.x = acc[mi][ni][2] + b0; v1.y = acc[mi][ni][3] + b1;
            *(float2*)&C[(size_t)r0       * GG + cb] = v0;
            *(float2*)&C[(size_t)(r0 + 8) * GG + cb] = v1;
        }
    }
}

// ---------------- persistent tf32 recurrent engine ---------------------------
// Block: NC = NI*8 gate-cols = 4 gates x NU units (NU = NI*2).
// 8 warps K-split (64 k each). U fragments live in REGISTERS (loaded once).
// H[64,512] loaded to smem each step (coalesced), A-frags conflict-free.
// Partials reduced via padded z-slab; cell state in registers.
template<int NI>
__device__ __forceinline__ void rec_run(
    const float* __restrict__ xw, const float* __restrict__ U,
    float* __restrict__ seq, int u0, bool rev, unsigned nblocks,
    unsigned* smem)
{
    constexpr int NU = NI * 2;                     // units per block
    constexpr int ZP = (NI == 2) ? 20 : 36;        // z-slab pad (conflict-free)

    unsigned (*Hs)[516] = (unsigned(*)[516])smem;  // [b][k], pad 516
    float* zslab = (float*)(smem + 64 * 516);      // [8][64][ZP]

    const int tid  = threadIdx.x;
    const int warp = tid >> 5, lane = tid & 31;
    const int g    = lane >> 2, t = lane & 3;

    // ---- U fragments -> registers (once) ----
    unsigned bf[8][NI][2];
#pragma unroll
    for (int s = 0; s < 8; s++)
#pragma unroll
        for (int ni = 0; ni < NI; ni++) {
            const int c    = ni * 8 + g;
            const int gate = c / NU, uu = c % NU;
            const size_t ncol = (size_t)gate * DD + u0 + uu;
            const int kg = warp * 64 + s * 8 + t;
            bf[s][ni][0] = f2tf(U[(size_t)kg * GG + ncol]);
            bf[s][ni][1] = f2tf(U[(size_t)(kg + 4) * GG + ncol]);
        }

    const int gb = tid >> 2, gdu = tid & 3;        // gate-phase mapping
    float creg[NI / 2];
#pragma unroll
    for (int i = 0; i < NI / 2; i++) creg[i] = 0.f;

    for (int st = 0; st < TT; st++) {
        const int tout  = rev ? (TT - 1 - st) : st;
        const int tprev = (st == 0) ? -1 : (rev ? tout + 1 : tout - 1);

        // prefetch xw for the gate phase (hides DRAM latency behind mma)
        float xwv[NI * 2];
#pragma unroll
        for (int ui = 0; ui < NI / 2; ui++)
#pragma unroll
            for (int gate = 0; gate < 4; gate++)
                xwv[ui * 4 + gate] =
                    xw[((size_t)gb * TT + tout) * GG + (size_t)gate * DD + u0 + gdu + ui * 4];

        float acc[4][NI][4];
#pragma unroll
        for (int mi = 0; mi < 4; mi++)
#pragma unroll
            for (int ni = 0; ni < NI; ni++)
#pragma unroll
                for (int r = 0; r < 4; r++) acc[mi][ni][r] = 0.f;

        if (tprev >= 0) {
            // load H[64,512] -> Hs (tf32), coalesced
#pragma unroll 4
            for (int i = 0; i < 32; i++) {
                const int e = i * 256 + tid;
                const int b = e >> 7, k4 = (e & 127) << 2;
                float4 h4 = *(const float4*)&seq[((size_t)b * TT + tprev) * DD + k4];
                uint4 u; u.x = f2tf(h4.x); u.y = f2tf(h4.y);
                         u.z = f2tf(h4.z); u.w = f2tf(h4.w);
                *(uint4*)&Hs[b][k4] = u;
            }
            __syncthreads();

#pragma unroll
            for (int s = 0; s < 8; s++) {
                const int kk = warp * 64 + s * 8;
                unsigned af[4][4];
#pragma unroll
                for (int mi = 0; mi < 4; mi++) {
                    const int r = mi * 16;
                    af[mi][0] = Hs[r + g    ][kk + t];
                    af[mi][1] = Hs[r + g + 8][kk + t];
                    af[mi][2] = Hs[r + g    ][kk + t + 4];
                    af[mi][3] = Hs[r + g + 8][kk + t + 4];
                }
#pragma unroll
                for (int mi = 0; mi < 4; mi++)
#pragma unroll
                    for (int ni = 0; ni < NI; ni++)
                        mma_tf32(acc[mi][ni], af[mi], bf[s][ni]);
            }
        }

        // store partials to z-slab
        {
            float* zs = zslab + (size_t)warp * 64 * ZP;
#pragma unroll
            for (int mi = 0; mi < 4; mi++)
#pragma unroll
                for (int ni = 0; ni < NI; ni++) {
                    const int r = mi * 16 + g, c = ni * 8 + 2 * t;
                    zs[(size_t)r * ZP + c]           = acc[mi][ni][0];
                    zs[(size_t)r * ZP + c + 1]       = acc[mi][ni][1];
                    zs[(size_t)(r + 8) * ZP + c]     = acc[mi][ni][2];
                    zs[(size_t)(r + 8) * ZP + c + 1] = acc[mi][ni][3];
                }
        }
        __syncthreads();

        // reduce 8 warps + gates + h store; cell state in registers
#pragma unroll
        for (int ui = 0; ui < NI / 2; ui++) {
            const int uu = gdu + ui * 4;
            float z[4];
#pragma unroll
            for (int gate = 0; gate < 4; gate++) {
                const int c = gate * NU + uu;
                float ssum = 0.f;
#pragma unroll
                for (int w = 0; w < 8; w++)
                    ssum += zslab[(size_t)w * 64 * ZP + (size_t)gb * ZP + c];
                z[gate] = ssum + xwv[ui * 4 + gate];
            }
            const float si = 1.f / (1.f + __expf(-z[0]));
            const float sf = 1.f / (1.f + __expf(-z[1]));
            const float so = 1.f / (1.f + __expf(-z[3]));
            const float gr = fmaxf(z[2], 0.f);
            const float cn = sf * creg[ui] + si * gr;
            creg[ui] = cn;
            seq[((size_t)gb * TT + tout) * DD + u0 + uu] = so * fmaxf(cn, 0.f);
        }

        if (st < TT - 1) grid_barrier(nblocks);
    }
}

extern __shared__ unsigned dsm[];

// layer 1: 128 blocks x 4 units
__global__ void __launch_bounds__(256) k_rec1(
    const float* __restrict__ xw, const float* __restrict__ U,
    float* __restrict__ seq)
{
    rec_run<2>(xw, U, seq, blockIdx.x * 4, false, gridDim.x, dsm);
}

// layer 2: blocks 0-63 forward, 64-127 backward, 8 units each
__global__ void __launch_bounds__(256) k_rec2(
    const float* __restrict__ xwf, const float* __restrict__ Uf,
    float* __restrict__ hf,
    const float* __restrict__ xwb, const float* __restrict__ Ub,
    float* __restrict__ hb)
{
    const int u0 = (blockIdx.x & 63) * 8;
    if (blockIdx.x < 64) rec_run<4>(xwf, Uf, hf, u0, false, gridDim.x, dsm);
    else                 rec_run<4>(xwb, Ub, hb, u0, true,  gridDim.x, dsm);
}

#define SMEM_REC1 (64*516*4 + 8*64*20*4)   // 173056
#define SMEM_REC2 (64*516*4 + 8*64*36*4)   // 205824

// ---------------- LayerNorm(concat(hf,hb)) * gamma + beta + residual --------
__global__ void __launch_bounds__(256) k_ln_residual(
    const float* __restrict__ x, const float* __restrict__ gamma,
    const float* __restrict__ beta, const float* __restrict__ hf,
    const float* __restrict__ hb, float* __restrict__ out)
{
    const int bt  = blockIdx.x;
    const int tid = threadIdx.x;
    const float* hfr = hf + (size_t)bt * DD;
    const float* hbr = hb + (size_t)bt * DD;

    float v[4];
    float s = 0.f;
#pragma unroll
    for (int r = 0; r < 4; r++) {
        int i = tid + r * 256;
        float val = (i < DD) ? hfr[i] : hbr[i - DD];
        v[r] = val; s += val;
    }

    __shared__ float rbuf[8];
    __shared__ float stat[2];
    const int lane = tid & 31, w = tid >> 5;
#pragma unroll
    for (int o = 16; o; o >>= 1) s += __shfl_xor_sync(0xffffffffu, s, o);
    if (lane == 0) rbuf[w] = s;
    __syncthreads();
    if (tid == 0) {
        float tsum = 0.f;
        for (int i = 0; i < 8; i++) tsum += rbuf[i];
        stat[0] = tsum * (1.f / 1024.f);
    }
    __syncthreads();
    const float mean = stat[0];

    float s2 = 0.f;
#pragma unroll
    for (int r = 0; r < 4; r++) { float d = v[r] - mean; s2 += d * d; }
#pragma unroll
    for (int o = 16; o; o >>= 1) s2 += __shfl_xor_sync(0xffffffffu, s2, o);
    if (lane == 0) rbuf[w] = s2;
    __syncthreads();
    if (tid == 0) {
        float tsum = 0.f;
        for (int i = 0; i < 8; i++) tsum += rbuf[i];
        stat[1] = rsqrtf(tsum * (1.f / 1024.f) + 1e-6f);
    }
    __syncthreads();
    const float rstd = stat[1];

    const float* xr  = x   + (size_t)bt * II;
    float*       otr = out + (size_t)bt * II;
#pragma unroll
    for (int r = 0; r < 4; r++) {
        int i = tid + r * 256;
        otr[i] = xr[i] + (v[r] - mean) * rstd * gamma[i] + beta[i];
    }
}

// ---------------- launcher ---------------------------------------------------
extern "C" void kernel_launch(void* const* d_in, const int* in_sizes, int n_in,
                              void* d_out, int out_size)
{
    (void)in_sizes; (void)n_in; (void)out_size;
    const float* x     = (const float*)d_in[0];
    const float* W1    = (const float*)d_in[1];
    const float* U1    = (const float*)d_in[2];
    const float* b1    = (const float*)d_in[3];
    const float* Wf    = (const float*)d_in[4];
    const float* Uf    = (const float*)d_in[5];
    const float* bf    = (const float*)d_in[6];
    const float* Wb    = (const float*)d_in[7];
    const float* Ub    = (const float*)d_in[8];
    const float* bb    = (const float*)d_in[9];
    const float* gamma = (const float*)d_in[10];
    const float* beta  = (const float*)d_in[11];
    float* out = (float*)d_out;

    float *xw1, *xwf, *xwb, *h1, *hf, *hb;
    cudaGetSymbolAddress((void**)&xw1, g_xw1);
    cudaGetSymbolAddress((void**)&xwf, g_xwf);
    cudaGetSymbolAddress((void**)&xwb, g_xwb);
    cudaGetSymbolAddress((void**)&h1,  g_h1);
    cudaGetSymbolAddress((void**)&hf,  g_hf);
    cudaGetSymbolAddress((void**)&hb,  g_hb);

    cudaFuncSetAttribute(k_rec1, cudaFuncAttributeMaxDynamicSharedMemorySize, SMEM_REC1);
    cudaFuncSetAttribute(k_rec2, cudaFuncAttributeMaxDynamicSharedMemorySize, SMEM_REC2);

    dim3 ggrid(GG / 128, BT / 128);   // (16, 256)

    k_mma_gemm<<<ggrid, 256>>>(x, W1, b1, xw1, II);
    k_rec1<<<128, 256, SMEM_REC1>>>(xw1, U1, h1);
    k_mma_gemm<<<ggrid, 256>>>(h1, Wf, bf, xwf, DD);
    k_mma_gemm<<<ggrid, 256>>>(h1, Wb, bb, xwb, DD);
    k_rec2<<<128, 256, SMEM_REC2>>>(xwf, Uf, hf, xwb, Ub, hb);
    k_ln_residual<<<BT, 256>>>(x, gamma, beta, hf, hb, out);
}

// round 8
// speedup vs baseline: 3.0869x; 1.1277x over previous
#include <cuda_runtime.h>
#include <math.h>

#define BB 64
#define TT 512
#define DD 512
#define II 1024
#define GG 2048                 // 4*D
#define BT (BB*TT)              // 32768

// ---------------- device scratch (static: allocation-free at run time) ------
__device__ float    g_xw1[BT * GG];   // x  @ W1 + b1   [B,T,4D]
__device__ float    g_xwf[BT * GG];   // h1 @ Wf + bf
__device__ float    g_xwb[BT * GG];   // h1 @ Wb + bb
__device__ float    g_h1 [BT * DD];   // layer-1 hidden sequence (float, for GEMM)
__device__ float    g_hf [BT * DD];   // forward hidden sequence (float, for LN)
__device__ float    g_hb [BT * DD];   // backward hidden sequence (float, for LN)
__device__ unsigned g_h1t[BT * DD];   // tf32 bit-pattern copies (for recurrent mma)
__device__ unsigned g_hft[BT * DD];
__device__ unsigned g_hbt[BT * DD];

// ---------------- software grid barriers (per chain) -------------------------
__device__ unsigned g_cnt1 = 0, g_gen1 = 0;     // layer-1 chain (128 blocks)
__device__ unsigned g_cntF = 0, g_genF = 0;     // layer-2 forward (64 blocks)
__device__ unsigned g_cntB = 0, g_genB = 0;     // layer-2 backward (64 blocks)

__device__ __forceinline__ void grid_barrier(unsigned* cnt, unsigned* gen, unsigned nb) {
    __threadfence();            // release h[t] writes device-wide
    __syncthreads();
    if (threadIdx.x == 0) {
        unsigned g0 = *((volatile unsigned*)gen);
        unsigned a  = atomicAdd(cnt, 1);
        if (a == nb - 1) {
            *cnt = 0;           // safe: nobody re-arrives until gen bumps
            __threadfence();
            atomicAdd(gen, 1);
        } else {
            while (*((volatile unsigned*)gen) == g0) { }
        }
        __threadfence();        // acquire
    }
    __syncthreads();
}

// ---------------- tf32 helpers ----------------------------------------------
__device__ __forceinline__ unsigned f2tf(float f) {
    unsigned r; asm("cvt.rna.tf32.f32 %0, %1;" : "=r"(r) : "f"(f)); return r;
}

__device__ __forceinline__ void mma_tf32(float* d, const unsigned* a, const unsigned* b) {
    asm volatile("mma.sync.aligned.m16n8k8.row.col.f32.tf32.tf32.f32 "
        "{%0,%1,%2,%3}, {%4,%5,%6,%7}, {%8,%9}, {%0,%1,%2,%3};\n"
        : "+f"(d[0]), "+f"(d[1]), "+f"(d[2]), "+f"(d[3])
        : "r"(a[0]), "r"(a[1]), "r"(a[2]), "r"(a[3]), "r"(b[0]), "r"(b[1]));
}

// ---------------- tf32 MMA GEMM: C[BT,GG] = A[BT,K] @ W[K,GG] + bias --------
// 128x128 block tile, k-chunk 32, 8 warps (2m x 4n), warp tile 64x32.
__global__ void __launch_bounds__(256) k_mma_gemm(
    const float* __restrict__ A, const float* __restrict__ W,
    const float* __restrict__ bias, float* __restrict__ C, int K)
{
    __shared__ unsigned As[128][36];
    __shared__ unsigned Bs[32][136];

    const int tid  = threadIdx.x;
    const int warp = tid >> 5, lane = tid & 31;
    const int g    = lane >> 2, t = lane & 3;
    const int wm   = (warp >> 2) * 64;
    const int wn   = (warp & 3) * 32;
    const int row0 = blockIdx.y * 128, col0 = blockIdx.x * 128;

    const int a_m  = tid >> 3;
    const int a_k4 = (tid & 7) * 4;
    const int b_k  = tid >> 5;
    const int b_n4 = (tid & 31) * 4;

    float acc[4][4][4];
#pragma unroll
    for (int mi = 0; mi < 4; mi++)
#pragma unroll
        for (int ni = 0; ni < 4; ni++)
#pragma unroll
            for (int r = 0; r < 4; r++) acc[mi][ni][r] = 0.f;

    const float* Ap = A + (size_t)(row0 + a_m) * K + a_k4;
    const float* Wp = W + (size_t)b_k * GG + col0 + b_n4;

    float4 av[4], bv[4];
#pragma unroll
    for (int i = 0; i < 4; i++) av[i] = *(const float4*)(Ap + (size_t)(i * 32) * K);
#pragma unroll
    for (int i = 0; i < 4; i++) bv[i] = *(const float4*)(Wp + (size_t)(i * 8) * GG);

    for (int k0 = 0; k0 < K; k0 += 32) {
        __syncthreads();
#pragma unroll
        for (int i = 0; i < 4; i++) {
            uint4 u; u.x = f2tf(av[i].x); u.y = f2tf(av[i].y);
                     u.z = f2tf(av[i].z); u.w = f2tf(av[i].w);
            *(uint4*)&As[i * 32 + a_m][a_k4] = u;
        }
#pragma unroll
        for (int i = 0; i < 4; i++) {
            uint4 u; u.x = f2tf(bv[i].x); u.y = f2tf(bv[i].y);
                     u.z = f2tf(bv[i].z); u.w = f2tf(bv[i].w);
            *(uint4*)&Bs[i * 8 + b_k][b_n4] = u;
        }
        if (k0 + 32 < K) {
#pragma unroll
            for (int i = 0; i < 4; i++)
                av[i] = *(const float4*)(Ap + (size_t)(i * 32) * K + (k0 + 32));
#pragma unroll
            for (int i = 0; i < 4; i++)
                bv[i] = *(const float4*)(Wp + (size_t)(k0 + 32 + i * 8) * GG);
        }
        __syncthreads();

#pragma unroll
        for (int s = 0; s < 4; s++) {
            const int kk = s * 8;
            unsigned af[4][4];
#pragma unroll
            for (int mi = 0; mi < 4; mi++) {
                const int r = wm + mi * 16;
                af[mi][0] = As[r + g    ][kk + t];
                af[mi][1] = As[r + g + 8][kk + t];
                af[mi][2] = As[r + g    ][kk + t + 4];
                af[mi][3] = As[r + g + 8][kk + t + 4];
            }
            unsigned bf[4][2];
#pragma unroll
            for (int ni = 0; ni < 4; ni++) {
                bf[ni][0] = Bs[kk + t    ][wn + ni * 8 + g];
                bf[ni][1] = Bs[kk + t + 4][wn + ni * 8 + g];
            }
#pragma unroll
            for (int mi = 0; mi < 4; mi++)
#pragma unroll
                for (int ni = 0; ni < 4; ni++)
                    mma_tf32(acc[mi][ni], af[mi], bf[ni]);
        }
    }

#pragma unroll
    for (int mi = 0; mi < 4; mi++) {
        const int r0 = row0 + wm + mi * 16 + g;
#pragma unroll
        for (int ni = 0; ni < 4; ni++) {
            const int cb = col0 + wn + ni * 8 + 2 * t;
            const float b0 = bias[cb], b1 = bias[cb + 1];
            float2 v0; v0.x = acc[mi][ni][0] + b0; v0.y = acc[mi][ni][1] + b1;
            float2 v1; v1.x = acc[mi][ni][2] + b0; v1.y = acc[mi][ni][3] + b1;
            *(float2*)&C[(size_t)r0       * GG + cb] = v0;
            *(float2*)&C[(size_t)(r0 + 8) * GG + cb] = v1;
        }
    }
}

// ---------------- persistent tf32 recurrent engine ---------------------------
// Block: NI*8 gate-cols = 4 gates x NU units (NU = NI*2).
// 8 warps K-split (64 k each). U fragments live in REGISTERS (loaded once).
// H comes from the tf32 shadow buffer -> pure LDG.128/STS.128 staging, no cvt.
// Partials reduced via padded z-slab; cell state in registers.
template<int NI>
__device__ __forceinline__ void rec_run(
    const float* __restrict__ xw, const float* __restrict__ U,
    float* __restrict__ seq, unsigned* __restrict__ seqt,
    int u0, bool rev, unsigned nblocks,
    unsigned* cnt, unsigned* gen, unsigned* smem)
{
    constexpr int NU = NI * 2;
    constexpr int ZP = (NI == 2) ? 20 : 36;

    unsigned (*Hs)[516] = (unsigned(*)[516])smem;   // [b][k], pad 516
    float* zslab = (float*)(smem + 64 * 516);       // [8][64][ZP]

    const int tid  = threadIdx.x;
    const int warp = tid >> 5, lane = tid & 31;
    const int g    = lane >> 2, t = lane & 3;

    // ---- U fragments -> registers (once) ----
    unsigned bf[8][NI][2];
#pragma unroll
    for (int s = 0; s < 8; s++)
#pragma unroll
        for (int ni = 0; ni < NI; ni++) {
            const int c    = ni * 8 + g;
            const int gate = c / NU, uu = c % NU;
            const size_t ncol = (size_t)gate * DD + u0 + uu;
            const int kg = warp * 64 + s * 8 + t;
            bf[s][ni][0] = f2tf(U[(size_t)kg * GG + ncol]);
            bf[s][ni][1] = f2tf(U[(size_t)(kg + 4) * GG + ncol]);
        }

    const int gb = tid >> 2, gdu = tid & 3;
    float creg[NI / 2];
#pragma unroll
    for (int i = 0; i < NI / 2; i++) creg[i] = 0.f;

    for (int st = 0; st < TT; st++) {
        const int tout  = rev ? (TT - 1 - st) : st;
        const int tprev = (st == 0) ? -1 : (rev ? tout + 1 : tout - 1);

        // prefetch xw for the gate phase (hides latency behind mma)
        float xwv[NI * 2];
#pragma unroll
        for (int ui = 0; ui < NI / 2; ui++)
#pragma unroll
            for (int gate = 0; gate < 4; gate++)
                xwv[ui * 4 + gate] =
                    xw[((size_t)gb * TT + tout) * GG + (size_t)gate * DD + u0 + gdu + ui * 4];

        float acc[4][NI][4];
#pragma unroll
        for (int mi = 0; mi < 4; mi++)
#pragma unroll
            for (int ni = 0; ni < NI; ni++)
#pragma unroll
                for (int r = 0; r < 4; r++) acc[mi][ni][r] = 0.f;

        if (tprev >= 0) {
            // load H[64,512] (tf32 bits) -> Hs, pure LDG/STS, no cvt
#pragma unroll 8
            for (int i = 0; i < 32; i++) {
                const int e = i * 256 + tid;
                const int b = e >> 7, k4 = (e & 127) << 2;
                uint4 u = *(const uint4*)&seqt[((size_t)b * TT + tprev) * DD + k4];
                *(uint4*)&Hs[b][k4] = u;
            }
            __syncthreads();

#pragma unroll
            for (int s = 0; s < 8; s++) {
                const int kk = warp * 64 + s * 8;
                unsigned af[4][4];
#pragma unroll
                for (int mi = 0; mi < 4; mi++) {
                    const int r = mi * 16;
                    af[mi][0] = Hs[r + g    ][kk + t];
                    af[mi][1] = Hs[r + g + 8][kk + t];
                    af[mi][2] = Hs[r + g    ][kk + t + 4];
                    af[mi][3] = Hs[r + g + 8][kk + t + 4];
                }
#pragma unroll
                for (int mi = 0; mi < 4; mi++)
#pragma unroll
                    for (int ni = 0; ni < NI; ni++)
                        mma_tf32(acc[mi][ni], af[mi], bf[s][ni]);
            }
        }

        // store partials to z-slab
        {
            float* zs = zslab + (size_t)warp * 64 * ZP;
#pragma unroll
            for (int mi = 0; mi < 4; mi++)
#pragma unroll
                for (int ni = 0; ni < NI; ni++) {
                    const int r = mi * 16 + g, c = ni * 8 + 2 * t;
                    zs[(size_t)r * ZP + c]           = acc[mi][ni][0];
                    zs[(size_t)r * ZP + c + 1]       = acc[mi][ni][1];
                    zs[(size_t)(r + 8) * ZP + c]     = acc[mi][ni][2];
                    zs[(size_t)(r + 8) * ZP + c + 1] = acc[mi][ni][3];
                }
        }
        __syncthreads();

        // reduce 8 warps + gates + h store; cell state in registers
#pragma unroll
        for (int ui = 0; ui < NI / 2; ui++) {
            const int uu = gdu + ui * 4;
            float z[4];
#pragma unroll
            for (int gate = 0; gate < 4; gate++) {
                const int c = gate * NU + uu;
                float ssum = 0.f;
#pragma unroll
                for (int w = 0; w < 8; w++)
                    ssum += zslab[(size_t)w * 64 * ZP + (size_t)gb * ZP + c];
                z[gate] = ssum + xwv[ui * 4 + gate];
            }
            const float si = 1.f / (1.f + __expf(-z[0]));
            const float sf = 1.f / (1.f + __expf(-z[1]));
            const float so = 1.f / (1.f + __expf(-z[3]));
            const float gr = fmaxf(z[2], 0.f);
            const float cn = sf * creg[ui] + si * gr;
            creg[ui] = cn;
            const float hv = so * fmaxf(cn, 0.f);
            const size_t idx = ((size_t)gb * TT + tout) * DD + u0 + uu;
            seq [idx] = hv;
            seqt[idx] = f2tf(hv);
        }

        if (st < TT - 1) grid_barrier(cnt, gen, nblocks);
    }
}

extern __shared__ unsigned dsm[];

// layer 1: 128 blocks x 4 units, one chain
__global__ void __launch_bounds__(256) k_rec1(
    const float* __restrict__ xw, const float* __restrict__ U,
    float* __restrict__ seq, unsigned* __restrict__ seqt)
{
    rec_run<2>(xw, U, seq, seqt, blockIdx.x * 4, false, gridDim.x,
               &g_cnt1, &g_gen1, dsm);
}

// layer 2: blocks 0-63 forward, 64-127 backward, 8 units each.
// Each direction has its OWN barrier (independent chains).
__global__ void __launch_bounds__(256) k_rec2(
    const float* __restrict__ xwf, const float* __restrict__ Uf,
    float* __restrict__ hf, unsigned* __restrict__ hft,
    const float* __restrict__ xwb, const float* __restrict__ Ub,
    float* __restrict__ hb, unsigned* __restrict__ hbt)
{
    const int u0 = (blockIdx.x & 63) * 8;
    if (blockIdx.x < 64)
        rec_run<4>(xwf, Uf, hf, hft, u0, false, 64, &g_cntF, &g_genF, dsm);
    else
        rec_run<4>(xwb, Ub, hb, hbt, u0, true,  64, &g_cntB, &g_genB, dsm);
}

#define SMEM_REC1 (64*516*4 + 8*64*20*4)   // 173056
#define SMEM_REC2 (64*516*4 + 8*64*36*4)   // 205824

// ---------------- LayerNorm(concat(hf,hb)) * gamma + beta + residual --------
__global__ void __launch_bounds__(256) k_ln_residual(
    const float* __restrict__ x, const float* __restrict__ gamma,
    const float* __restrict__ beta, const float* __restrict__ hf,
    const float* __restrict__ hb, float* __restrict__ out)
{
    const int bt  = blockIdx.x;
    const int tid = threadIdx.x;
    const float* hfr = hf + (size_t)bt * DD;
    const float* hbr = hb + (size_t)bt * DD;

    float v[4];
    float s = 0.f;
#pragma unroll
    for (int r = 0; r < 4; r++) {
        int i = tid + r * 256;
        float val = (i < DD) ? hfr[i] : hbr[i - DD];
        v[r] = val; s += val;
    }

    __shared__ float rbuf[8];
    __shared__ float stat[2];
    const int lane = tid & 31, w = tid >> 5;
#pragma unroll
    for (int o = 16; o; o >>= 1) s += __shfl_xor_sync(0xffffffffu, s, o);
    if (lane == 0) rbuf[w] = s;
    __syncthreads();
    if (tid == 0) {
        float tsum = 0.f;
        for (int i = 0; i < 8; i++) tsum += rbuf[i];
        stat[0] = tsum * (1.f / 1024.f);
    }
    __syncthreads();
    const float mean = stat[0];

    float s2 = 0.f;
#pragma unroll
    for (int r = 0; r < 4; r++) { float d = v[r] - mean; s2 += d * d; }
#pragma unroll
    for (int o = 16; o; o >>= 1) s2 += __shfl_xor_sync(0xffffffffu, s2, o);
    if (lane == 0) rbuf[w] = s2;
    __syncthreads();
    if (tid == 0) {
        float tsum = 0.f;
        for (int i = 0; i < 8; i++) tsum += rbuf[i];
        stat[1] = rsqrtf(tsum * (1.f / 1024.f) + 1e-6f);
    }
    __syncthreads();
    const float rstd = stat[1];

    const float* xr  = x   + (size_t)bt * II;
    float*       otr = out + (size_t)bt * II;
#pragma unroll
    for (int r = 0; r < 4; r++) {
        int i = tid + r * 256;
        otr[i] = xr[i] + (v[r] - mean) * rstd * gamma[i] + beta[i];
    }
}

// ---------------- launcher ---------------------------------------------------
extern "C" void kernel_launch(void* const* d_in, const int* in_sizes, int n_in,
                              void* d_out, int out_size)
{
    (void)in_sizes; (void)n_in; (void)out_size;
    const float* x     = (const float*)d_in[0];
    const float* W1    = (const float*)d_in[1];
    const float* U1    = (const float*)d_in[2];
    const float* b1    = (const float*)d_in[3];
    const float* Wf    = (const float*)d_in[4];
    const float* Uf    = (const float*)d_in[5];
    const float* bf    = (const float*)d_in[6];
    const float* Wb    = (const float*)d_in[7];
    const float* Ub    = (const float*)d_in[8];
    const float* bb    = (const float*)d_in[9];
    const float* gamma = (const float*)d_in[10];
    const float* beta  = (const float*)d_in[11];
    float* out = (float*)d_out;

    float *xw1, *xwf, *xwb, *h1, *hf, *hb;
    unsigned *h1t, *hft, *hbt;
    cudaGetSymbolAddress((void**)&xw1, g_xw1);
    cudaGetSymbolAddress((void**)&xwf, g_xwf);
    cudaGetSymbolAddress((void**)&xwb, g_xwb);
    cudaGetSymbolAddress((void**)&h1,  g_h1);
    cudaGetSymbolAddress((void**)&hf,  g_hf);
    cudaGetSymbolAddress((void**)&hb,  g_hb);
    cudaGetSymbolAddress((void**)&h1t, g_h1t);
    cudaGetSymbolAddress((void**)&hft, g_hft);
    cudaGetSymbolAddress((void**)&hbt, g_hbt);

    cudaFuncSetAttribute(k_rec1, cudaFuncAttributeMaxDynamicSharedMemorySize, SMEM_REC1);
    cudaFuncSetAttribute(k_rec2, cudaFuncAttributeMaxDynamicSharedMemorySize, SMEM_REC2);

    dim3 ggrid(GG / 128, BT / 128);   // (16, 256)

    k_mma_gemm<<<ggrid, 256>>>(x, W1, b1, xw1, II);
    k_rec1<<<128, 256, SMEM_REC1>>>(xw1, U1, h1, h1t);
    k_mma_gemm<<<ggrid, 256>>>(h1, Wf, bf, xwf, DD);
    k_mma_gemm<<<ggrid, 256>>>(h1, Wb, bb, xwb, DD);
    k_rec2<<<128, 256, SMEM_REC2>>>(xwf, Uf, hf, hft, xwb, Ub, hb, hbt);
    k_ln_residual<<<BT, 256>>>(x, gamma, beta, hf, hb, out);
}

// round 9
// speedup vs baseline: 3.9703x; 1.2862x over previous
#include <cuda_runtime.h>
#include <math.h>

#define BB 64
#define TT 512
#define DD 512
#define II 1024
#define GG 2048                 // 4*D
#define BT (BB*TT)              // 32768

// ---------------- device scratch (static: allocation-free at run time) ------
__device__ float    g_xw1[BT * GG];
__device__ float    g_xwf[BT * GG];
__device__ float    g_xwb[BT * GG];
__device__ float    g_h1 [BT * DD];
__device__ float    g_hf [BT * DD];
__device__ float    g_hb [BT * DD];
__device__ unsigned g_h1t[BT * DD];   // tf32 shadow copies for recurrent mma
__device__ unsigned g_hft[BT * DD];
__device__ unsigned g_hbt[BT * DD];

// ---------------- per-group software barriers (32 arrivals each) -------------
// slot: [grp][0]=cnt, [grp][1]=gen; 128B stride between groups
__device__ unsigned g_bar[4][32];

__device__ __forceinline__ void group_barrier(int grp, unsigned nb) {
    __threadfence();
    __syncthreads();
    if (threadIdx.x == 0) {
        unsigned* cnt = &g_bar[grp][0];
        unsigned* gen = &g_bar[grp][1];
        unsigned g0 = *((volatile unsigned*)gen);
        unsigned a  = atomicAdd(cnt, 1);
        if (a == nb - 1) {
            *cnt = 0;
            __threadfence();
            atomicAdd(gen, 1);
        } else {
            while (*((volatile unsigned*)gen) == g0) { }
        }
        __threadfence();
    }
    __syncthreads();
}

// ---------------- tf32 / mma / ldmatrix helpers ------------------------------
__device__ __forceinline__ unsigned f2tf(float f) {
    unsigned r; asm("cvt.rna.tf32.f32 %0, %1;" : "=r"(r) : "f"(f)); return r;
}

__device__ __forceinline__ void mma_tf32(float* d, const unsigned* a, const unsigned* b) {
    asm volatile("mma.sync.aligned.m16n8k8.row.col.f32.tf32.tf32.f32 "
        "{%0,%1,%2,%3}, {%4,%5,%6,%7}, {%8,%9}, {%0,%1,%2,%3};\n"
        : "+f"(d[0]), "+f"(d[1]), "+f"(d[2]), "+f"(d[3])
        : "r"(a[0]), "r"(a[1]), "r"(a[2]), "r"(a[3]), "r"(b[0]), "r"(b[1]));
}

__device__ __forceinline__ void ldsm4(unsigned& r0, unsigned& r1, unsigned& r2,
                                      unsigned& r3, const unsigned* p) {
    unsigned addr = (unsigned)__cvta_generic_to_shared(p);
    asm volatile("ldmatrix.sync.aligned.m8n8.x4.shared.b16 {%0,%1,%2,%3}, [%4];"
        : "=r"(r0), "=r"(r1), "=r"(r2), "=r"(r3) : "r"(addr));
}

// sigmoid
__device__ __forceinline__ float sigm(float z) { return 1.f / (1.f + __expf(-z)); }

// ---------------- tf32 MMA GEMM: C[BT,GG] = A[BT,K] @ W[K,GG] + bias --------
__global__ void __launch_bounds__(256) k_mma_gemm(
    const float* __restrict__ A, const float* __restrict__ W,
    const float* __restrict__ bias, float* __restrict__ C, int K)
{
    __shared__ unsigned As[128][36];
    __shared__ unsigned Bs[32][136];

    const int tid  = threadIdx.x;
    const int warp = tid >> 5, lane = tid & 31;
    const int g    = lane >> 2, t = lane & 3;
    const int wm   = (warp >> 2) * 64;
    const int wn   = (warp & 3) * 32;
    const int row0 = blockIdx.y * 128, col0 = blockIdx.x * 128;

    const int a_m  = tid >> 3;
    const int a_k4 = (tid & 7) * 4;
    const int b_k  = tid >> 5;
    const int b_n4 = (tid & 31) * 4;

    float acc[4][4][4];
#pragma unroll
    for (int mi = 0; mi < 4; mi++)
#pragma unroll
        for (int ni = 0; ni < 4; ni++)
#pragma unroll
            for (int r = 0; r < 4; r++) acc[mi][ni][r] = 0.f;

    const float* Ap = A + (size_t)(row0 + a_m) * K + a_k4;
    const float* Wp = W + (size_t)b_k * GG + col0 + b_n4;

    float4 av[4], bv[4];
#pragma unroll
    for (int i = 0; i < 4; i++) av[i] = *(const float4*)(Ap + (size_t)(i * 32) * K);
#pragma unroll
    for (int i = 0; i < 4; i++) bv[i] = *(const float4*)(Wp + (size_t)(i * 8) * GG);

    for (int k0 = 0; k0 < K; k0 += 32) {
        __syncthreads();
#pragma unroll
        for (int i = 0; i < 4; i++) {
            uint4 u; u.x = f2tf(av[i].x); u.y = f2tf(av[i].y);
                     u.z = f2tf(av[i].z); u.w = f2tf(av[i].w);
            *(uint4*)&As[i * 32 + a_m][a_k4] = u;
        }
#pragma unroll
        for (int i = 0; i < 4; i++) {
            uint4 u; u.x = f2tf(bv[i].x); u.y = f2tf(bv[i].y);
                     u.z = f2tf(bv[i].z); u.w = f2tf(bv[i].w);
            *(uint4*)&Bs[i * 8 + b_k][b_n4] = u;
        }
        if (k0 + 32 < K) {
#pragma unroll
            for (int i = 0; i < 4; i++)
                av[i] = *(const float4*)(Ap + (size_t)(i * 32) * K + (k0 + 32));
#pragma unroll
            for (int i = 0; i < 4; i++)
                bv[i] = *(const float4*)(Wp + (size_t)(k0 + 32 + i * 8) * GG);
        }
        __syncthreads();

#pragma unroll
        for (int s = 0; s < 4; s++) {
            const int kk = s * 8;
            unsigned af[4][4];
#pragma unroll
            for (int mi = 0; mi < 4; mi++) {
                const int r = wm + mi * 16;
                af[mi][0] = As[r + g    ][kk + t];
                af[mi][1] = As[r + g + 8][kk + t];
                af[mi][2] = As[r + g    ][kk + t + 4];
                af[mi][3] = As[r + g + 8][kk + t + 4];
            }
            unsigned bfr[4][2];
#pragma unroll
            for (int ni = 0; ni < 4; ni++) {
                bfr[ni][0] = Bs[kk + t    ][wn + ni * 8 + g];
                bfr[ni][1] = Bs[kk + t + 4][wn + ni * 8 + g];
            }
#pragma unroll
            for (int mi = 0; mi < 4; mi++)
#pragma unroll
                for (int ni = 0; ni < 4; ni++)
                    mma_tf32(acc[mi][ni], af[mi], bfr[ni]);
        }
    }

#pragma unroll
    for (int mi = 0; mi < 4; mi++) {
        const int r0 = row0 + wm + mi * 16 + g;
#pragma unroll
        for (int ni = 0; ni < 4; ni++) {
            const int cb = col0 + wn + ni * 8 + 2 * t;
            const float b0 = bias[cb], b1 = bias[cb + 1];
            float2 v0; v0.x = acc[mi][ni][0] + b0; v0.y = acc[mi][ni][1] + b1;
            float2 v1; v1.x = acc[mi][ni][2] + b0; v1.y = acc[mi][ni][3] + b1;
            *(float2*)&C[(size_t)r0       * GG + cb] = v0;
            *(float2*)&C[(size_t)(r0 + 8) * GG + cb] = v1;
        }
    }
}

extern __shared__ unsigned dsm[];

// ---------------- layer-1 recurrence -----------------------------------------
// 128 blocks = 4 batch-groups x 32 col-groups. Block: 16 batches x 64 gate-cols
// (= 4 gates x 16 units). 8 warps K-split (64 k each). U frags in REGISTERS.
// Barrier: per batch-group, 32 arrivals.
#define H1W 516
#define Z1P 80
#define SMEM_REC1 (16*H1W*4 + 8*16*Z1P*4)    // 73984

__global__ void __launch_bounds__(256, 1) k_rec1(
    const float* __restrict__ xw, const float* __restrict__ U,
    float* __restrict__ seq, unsigned* __restrict__ seqt)
{
    unsigned (*Hs)[H1W] = (unsigned(*)[H1W])dsm;
    float* zslab = (float*)(dsm + 16 * H1W);       // [8][16][Z1P]

    const int bx = blockIdx.x;
    const int bg = bx & 3, cg = bx >> 2;
    const int bbase = bg * 16, u0 = cg * 16;

    const int tid  = threadIdx.x;
    const int warp = tid >> 5, lane = tid & 31;
    const int g    = lane >> 2, t = lane & 3;

    // U fragments -> registers (once)
    unsigned bfr[8][8][2];
#pragma unroll
    for (int s = 0; s < 8; s++)
#pragma unroll
        for (int ni = 0; ni < 8; ni++) {
            const int c = ni * 8 + g;
            const int gate = c >> 4, uu = c & 15;
            const size_t n = (size_t)gate * DD + u0 + uu;
            const int kg = warp * 64 + s * 8 + t;
            bfr[s][ni][0] = f2tf(U[(size_t)kg * GG + n]);
            bfr[s][ni][1] = f2tf(U[(size_t)(kg + 4) * GG + n]);
        }

    // ldmatrix lane addressing for A frags
    const int lt    = lane >> 3;
    const int arow  = ((lt & 1) << 3) + (lane & 7);
    const int akadd = (lt >> 1) << 2;

    const int gb = tid >> 4, guu = tid & 15;       // gate-phase mapping
    float c_reg = 0.f;

    for (int st = 0; st < TT; st++) {
        const int tout = st, tprev = st - 1;

        float xwv[4];
        {
            const size_t xrow = ((size_t)(bbase + gb) * TT + tout) * GG;
#pragma unroll
            for (int gate = 0; gate < 4; gate++)
                xwv[gate] = xw[xrow + (size_t)gate * DD + u0 + guu];
        }

        float acc[8][4];
#pragma unroll
        for (int ni = 0; ni < 8; ni++)
#pragma unroll
            for (int r = 0; r < 4; r++) acc[ni][r] = 0.f;

        if (tprev >= 0) {
            // stage H[16 batches, 512] tf32 -> smem (8 uint4 per thread)
#pragma unroll
            for (int i = 0; i < 8; i++) {
                const int e = i * 256 + tid;
                const int b = e >> 7, k4 = (e & 127) << 2;
                *(uint4*)&Hs[b][k4] =
                    *(const uint4*)&seqt[((size_t)(bbase + b) * TT + tprev) * DD + k4];
            }
            __syncthreads();

#pragma unroll
            for (int s = 0; s < 8; s++) {
                const int kk = warp * 64 + s * 8;
                unsigned af[4];
                ldsm4(af[0], af[1], af[2], af[3], &Hs[arow][kk + akadd]);
#pragma unroll
                for (int ni = 0; ni < 8; ni++)
                    mma_tf32(acc[ni], af, bfr[s][ni]);
            }
        }

        // write partials (own-warp slab; separate region from Hs)
        {
            float* zs = zslab + warp * 16 * Z1P;
#pragma unroll
            for (int ni = 0; ni < 8; ni++) {
                const int c = ni * 8 + 2 * t;
                float2 v0; v0.x = acc[ni][0]; v0.y = acc[ni][1];
                float2 v1; v1.x = acc[ni][2]; v1.y = acc[ni][3];
                *(float2*)&zs[(size_t)g       * Z1P + c] = v0;
                *(float2*)&zs[(size_t)(g + 8) * Z1P + c] = v1;
            }
        }
        __syncthreads();

        // reduce 8 warps + gates + h store
        {
            float z[4];
#pragma unroll
            for (int gate = 0; gate < 4; gate++) {
                const int cidx = gate * 16 + guu;
                float s = 0.f;
#pragma unroll
                for (int w = 0; w < 8; w++)
                    s += zslab[((size_t)w * 16 + gb) * Z1P + cidx];
                z[gate] = s + xwv[gate];
            }
            const float si = sigm(z[0]), sf = sigm(z[1]), so = sigm(z[3]);
            const float gr = fmaxf(z[2], 0.f);
            const float cn = sf * c_reg + si * gr;
            c_reg = cn;
            const float hv = so * fmaxf(cn, 0.f);
            const size_t idx = ((size_t)(bbase + gb) * TT + tout) * DD + u0 + guu;
            seq [idx] = hv;
            seqt[idx] = f2tf(hv);
        }

        if (st < TT - 1) group_barrier(bg, 32);
    }
}

// ---------------- layer-2 fused fwd/bwd recurrence ---------------------------
// 128 blocks: dir(2) x bg(2) x cg(32). Block: 32 batches x 64 gate-cols.
// U slice (512 x 64) in SMEM n-major; B frags via ldmatrix. zslab ALIASES Hs.
#define USW 516
#define Z2P 72
#define SMEM_REC2 (64*USW*4 + 8*32*Z2P*4)    // 132096 + 73728 = 205824

__global__ void __launch_bounds__(256, 1) k_rec2(
    const float* __restrict__ xwf, const float* __restrict__ Uf,
    float* __restrict__ hf, unsigned* __restrict__ hft,
    const float* __restrict__ xwb, const float* __restrict__ Ub,
    float* __restrict__ hb, unsigned* __restrict__ hbt)
{
    unsigned (*Us)[USW] = (unsigned(*)[USW])dsm;
    unsigned* shreg = dsm + 64 * USW;
    unsigned (*Hs)[USW] = (unsigned(*)[USW])shreg;   // [32][516]
    float* zslab = (float*)shreg;                    // [8][32][Z2P] (alias)

    const int bx  = blockIdx.x;
    const int dir = bx >> 6;
    const int bg2 = (bx >> 5) & 1, cg = bx & 31;
    const int grp = dir * 2 + bg2;
    const int bbase = bg2 * 32, u0 = cg * 16;

    const float* xw = dir ? xwb : xwf;
    const float* U  = dir ? Ub  : Uf;
    float*    seq   = dir ? hb  : hf;
    unsigned* seqt  = dir ? hbt : hft;

    const int tid  = threadIdx.x;
    const int warp = tid >> 5, lane = tid & 31;
    const int g    = lane >> 2, t = lane & 3;

    // stage U slice n-major into smem (once)
    for (int idx = tid; idx < 64 * 512; idx += 256) {
        const int col = idx >> 9, k = idx & 511;
        const int gate = col >> 4, uu = col & 15;
        Us[col][k] = f2tf(U[(size_t)k * GG + (size_t)gate * DD + u0 + uu]);
    }
    __syncthreads();

    // ldmatrix lane addressing
    const int lt    = lane >> 3;
    const int arow  = ((lt & 1) << 3) + (lane & 7);
    const int akadd = (lt >> 1) << 2;
    const int brow  = ((lt >> 1) << 3) + (lane & 7);   // + np*16
    const int bkadd = (lt & 1) << 2;

    const int gbb = tid >> 3, guu = tid & 7;
    float creg[2] = {0.f, 0.f};

    for (int st = 0; st < TT; st++) {
        const int tout  = dir ? (TT - 1 - st) : st;
        const int tprev = (st == 0) ? -1 : (dir ? tout + 1 : tout - 1);

        float xwv[8];
        {
            const size_t xrow = ((size_t)(bbase + gbb) * TT + tout) * GG;
#pragma unroll
            for (int ui = 0; ui < 2; ui++)
#pragma unroll
                for (int gate = 0; gate < 4; gate++)
                    xwv[ui * 4 + gate] =
                        xw[xrow + (size_t)gate * DD + u0 + guu + ui * 8];
        }

        float acc[2][8][4];
#pragma unroll
        for (int mi = 0; mi < 2; mi++)
#pragma unroll
            for (int ni = 0; ni < 8; ni++)
#pragma unroll
                for (int r = 0; r < 4; r++) acc[mi][ni][r] = 0.f;

        if (tprev >= 0) {
            // stage H[32 batches, 512] tf32 (16 uint4 per thread)
#pragma unroll
            for (int i = 0; i < 16; i++) {
                const int e = i * 256 + tid;
                const int b = e >> 7, k4 = (e & 127) << 2;
                *(uint4*)&Hs[b][k4] =
                    *(const uint4*)&seqt[((size_t)(bbase + b) * TT + tprev) * DD + k4];
            }
            __syncthreads();

#pragma unroll
            for (int s = 0; s < 8; s++) {
                const int kk = warp * 64 + s * 8;
                unsigned af[2][4];
#pragma unroll
                for (int mi = 0; mi < 2; mi++)
                    ldsm4(af[mi][0], af[mi][1], af[mi][2], af[mi][3],
                          &Hs[mi * 16 + arow][kk + akadd]);
                unsigned bfr[8][2];
#pragma unroll
                for (int np = 0; np < 4; np++) {
                    unsigned r0, r1, r2, r3;
                    ldsm4(r0, r1, r2, r3, &Us[np * 16 + brow][kk + bkadd]);
                    bfr[np * 2][0]     = r0; bfr[np * 2][1]     = r1;
                    bfr[np * 2 + 1][0] = r2; bfr[np * 2 + 1][1] = r3;
                }
#pragma unroll
                for (int mi = 0; mi < 2; mi++)
#pragma unroll
                    for (int ni = 0; ni < 8; ni++)
                        mma_tf32(acc[mi][ni], af[mi], bfr[ni]);
            }
            __syncthreads();   // all warps done reading Hs before zslab overwrites
        }

        // write partials into zslab (aliases Hs)
        {
            float* zs = zslab + warp * 32 * Z2P;
#pragma unroll
            for (int mi = 0; mi < 2; mi++)
#pragma unroll
                for (int ni = 0; ni < 8; ni++) {
                    const int r = mi * 16, c = ni * 8 + 2 * t;
                    float2 v0; v0.x = acc[mi][ni][0]; v0.y = acc[mi][ni][1];
                    float2 v1; v1.x = acc[mi][ni][2]; v1.y = acc[mi][ni][3];
                    *(float2*)&zs[(size_t)(r + g)     * Z2P + c] = v0;
                    *(float2*)&zs[(size_t)(r + g + 8) * Z2P + c] = v1;
                }
        }
        __syncthreads();

        // reduce + gates + h store (2 units per thread)
#pragma unroll
        for (int ui = 0; ui < 2; ui++) {
            const int unit = guu + ui * 8;
            float z[4];
#pragma unroll
            for (int gate = 0; gate < 4; gate++) {
                const int cidx = gate * 16 + unit;
                float s = 0.f;
#pragma unroll
                for (int w = 0; w < 8; w++)
                    s += zslab[((size_t)w * 32 + gbb) * Z2P + cidx];
                z[gate] = s + xwv[ui * 4 + gate];
            }
            const float si = sigm(z[0]), sf = sigm(z[1]), so = sigm(z[3]);
            const float gr = fmaxf(z[2], 0.f);
            const float cn = sf * creg[ui] + si * gr;
            creg[ui] = cn;
            const float hv = so * fmaxf(cn, 0.f);
            const size_t idx = ((size_t)(bbase + gbb) * TT + tout) * DD + u0 + unit;
            seq [idx] = hv;
            seqt[idx] = f2tf(hv);
        }

        if (st < TT - 1) group_barrier(grp, 32);
    }
}

// ---------------- LayerNorm(concat(hf,hb)) * gamma + beta + residual --------
__global__ void __launch_bounds__(256) k_ln_residual(
    const float* __restrict__ x, const float* __restrict__ gamma,
    const float* __restrict__ beta, const float* __restrict__ hf,
    const float* __restrict__ hb, float* __restrict__ out)
{
    const int bt  = blockIdx.x;
    const int tid = threadIdx.x;
    const float* hfr = hf + (size_t)bt * DD;
    const float* hbr = hb + (size_t)bt * DD;

    float v[4];
    float s = 0.f;
#pragma unroll
    for (int r = 0; r < 4; r++) {
        int i = tid + r * 256;
        float val = (i < DD) ? hfr[i] : hbr[i - DD];
        v[r] = val; s += val;
    }

    __shared__ float rbuf[8];
    __shared__ float stat[2];
    const int lane = tid & 31, w = tid >> 5;
#pragma unroll
    for (int o = 16; o; o >>= 1) s += __shfl_xor_sync(0xffffffffu, s, o);
    if (lane == 0) rbuf[w] = s;
    __syncthreads();
    if (tid == 0) {
        float tsum = 0.f;
        for (int i = 0; i < 8; i++) tsum += rbuf[i];
        stat[0] = tsum * (1.f / 1024.f);
    }
    __syncthreads();
    const float mean = stat[0];

    float s2 = 0.f;
#pragma unroll
    for (int r = 0; r < 4; r++) { float d = v[r] - mean; s2 += d * d; }
#pragma unroll
    for (int o = 16; o; o >>= 1) s2 += __shfl_xor_sync(0xffffffffu, s2, o);
    if (lane == 0) rbuf[w] = s2;
    __syncthreads();
    if (tid == 0) {
        float tsum = 0.f;
        for (int i = 0; i < 8; i++) tsum += rbuf[i];
        stat[1] = rsqrtf(tsum * (1.f / 1024.f) + 1e-6f);
    }
    __syncthreads();
    const float rstd = stat[1];

    const float* xr  = x   + (size_t)bt * II;
    float*       otr = out + (size_t)bt * II;
#pragma unroll
    for (int r = 0; r < 4; r++) {
        int i = tid + r * 256;
        otr[i] = xr[i] + (v[r] - mean) * rstd * gamma[i] + beta[i];
    }
}

// ---------------- launcher ---------------------------------------------------
extern "C" void kernel_launch(void* const* d_in, const int* in_sizes, int n_in,
                              void* d_out, int out_size)
{
    (void)in_sizes; (void)n_in; (void)out_size;
    const float* x     = (const float*)d_in[0];
    const float* W1    = (const float*)d_in[1];
    const float* U1    = (const float*)d_in[2];
    const float* b1    = (const float*)d_in[3];
    const float* Wf    = (const float*)d_in[4];
    const float* Uf    = (const float*)d_in[5];
    const float* bf    = (const float*)d_in[6];
    const float* Wb    = (const float*)d_in[7];
    const float* Ub    = (const float*)d_in[8];
    const float* bb    = (const float*)d_in[9];
    const float* gamma = (const float*)d_in[10];
    const float* beta  = (const float*)d_in[11];
    float* out = (float*)d_out;

    float *xw1, *xwf, *xwb, *h1, *hf, *hb;
    unsigned *h1t, *hft, *hbt;
    cudaGetSymbolAddress((void**)&xw1, g_xw1);
    cudaGetSymbolAddress((void**)&xwf, g_xwf);
    cudaGetSymbolAddress((void**)&xwb, g_xwb);
    cudaGetSymbolAddress((void**)&h1,  g_h1);
    cudaGetSymbolAddress((void**)&hf,  g_hf);
    cudaGetSymbolAddress((void**)&hb,  g_hb);
    cudaGetSymbolAddress((void**)&h1t, g_h1t);
    cudaGetSymbolAddress((void**)&hft, g_hft);
    cudaGetSymbolAddress((void**)&hbt, g_hbt);

    cudaFuncSetAttribute(k_rec1, cudaFuncAttributeMaxDynamicSharedMemorySize, SMEM_REC1);
    cudaFuncSetAttribute(k_rec2, cudaFuncAttributeMaxDynamicSharedMemorySize, SMEM_REC2);

    dim3 ggrid(GG / 128, BT / 128);   // (16, 256)

    k_mma_gemm<<<ggrid, 256>>>(x, W1, b1, xw1, II);
    k_rec1<<<128, 256, SMEM_REC1>>>(xw1, U1, h1, h1t);
    k_mma_gemm<<<ggrid, 256>>>(h1, Wf, bf, xwf, DD);
    k_mma_gemm<<<ggrid, 256>>>(h1, Wb, bb, xwb, DD);
    k_rec2<<<128, 256, SMEM_REC2>>>(xwf, Uf, hf, hft, xwb, Ub, hb, hbt);
    k_ln_residual<<<BT, 256>>>(x, gamma, beta, hf, hb, out);
}

// round 10
// speedup vs baseline: 4.2958x; 1.0820x over previous
#include <cuda_runtime.h>
#include <math.h>

#define BB 64
#define TT 512
#define DD 512
#define II 1024
#define GG 2048                 // 4*D
#define BT (BB*TT)              // 32768

// ---------------- device scratch (static: allocation-free at run time) ------
__device__ float    g_xw1[BT * GG];
__device__ float    g_xwf[BT * GG];
__device__ float    g_xwb[BT * GG];
__device__ float    g_h1 [BT * DD];
__device__ float    g_hf [BT * DD];
__device__ float    g_hb [BT * DD];
__device__ unsigned g_h1t[BT * DD];   // tf32 shadow copies for recurrent mma
__device__ unsigned g_hft[BT * DD];
__device__ unsigned g_hbt[BT * DD];

// ---------------- flag-based progress barriers -------------------------------
// flags[grp][blk*8]: monotonically increasing step counter, 32B-strided slots.
// Signal: syncthreads -> thread0 fence.acq_rel.gpu + relaxed store (step+1).
// Wait:   warp0 lanes poll all 32 blocks' flags (relaxed), one fence, bar.
__device__ unsigned g_flags1[4][256];   // layer-1: 4 batch-groups x 32 blocks
__device__ unsigned g_flags2[4][256];   // layer-2: (dir,bg) 4 groups x 32 blocks

__global__ void k_zero_flags() {
    int i = blockIdx.x * blockDim.x + threadIdx.x;
    if (i < 4 * 256) {
        g_flags1[i >> 8][i & 255] = 0;
        g_flags2[i >> 8][i & 255] = 0;
    }
}

__device__ __forceinline__ void bar_signal(unsigned* flagp, unsigned val) {
    __syncthreads();                         // all h-stores of this block done
    if (threadIdx.x == 0) {
        asm volatile("fence.acq_rel.gpu;" ::: "memory");
        asm volatile("st.relaxed.gpu.global.u32 [%0], %1;"
                     :: "l"(flagp), "r"(val) : "memory");
    }
}

__device__ __forceinline__ void bar_wait(const unsigned* flags, unsigned val) {
    if (threadIdx.x < 32) {
        const unsigned* p = flags + threadIdx.x * 8;
        unsigned v;
        do {
            asm volatile("ld.relaxed.gpu.global.u32 %0, [%1];"
                         : "=r"(v) : "l"(p));
        } while (__any_sync(0xffffffffu, (int)(v < val)));
        asm volatile("fence.acq_rel.gpu;" ::: "memory");
    }
    __syncthreads();
}

// ---------------- tf32 / mma / ldmatrix helpers ------------------------------
__device__ __forceinline__ unsigned f2tf(float f) {
    unsigned r; asm("cvt.rna.tf32.f32 %0, %1;" : "=r"(r) : "f"(f)); return r;
}

__device__ __forceinline__ void mma_tf32(float* d, const unsigned* a, const unsigned* b) {
    asm volatile("mma.sync.aligned.m16n8k8.row.col.f32.tf32.tf32.f32 "
        "{%0,%1,%2,%3}, {%4,%5,%6,%7}, {%8,%9}, {%0,%1,%2,%3};\n"
        : "+f"(d[0]), "+f"(d[1]), "+f"(d[2]), "+f"(d[3])
        : "r"(a[0]), "r"(a[1]), "r"(a[2]), "r"(a[3]), "r"(b[0]), "r"(b[1]));
}

__device__ __forceinline__ void ldsm4(unsigned& r0, unsigned& r1, unsigned& r2,
                                      unsigned& r3, const unsigned* p) {
    unsigned addr = (unsigned)__cvta_generic_to_shared(p);
    asm volatile("ldmatrix.sync.aligned.m8n8.x4.shared.b16 {%0,%1,%2,%3}, [%4];"
        : "=r"(r0), "=r"(r1), "=r"(r2), "=r"(r3) : "r"(addr));
}

__device__ __forceinline__ float sigm(float z) { return 1.f / (1.f + __expf(-z)); }

// ---------------- tf32 MMA GEMM: C[BT,GG] = A[BT,K] @ W[K,GG] + bias --------
__global__ void __launch_bounds__(256) k_mma_gemm(
    const float* __restrict__ A, const float* __restrict__ W,
    const float* __restrict__ bias, float* __restrict__ C, int K)
{
    __shared__ unsigned As[128][36];
    __shared__ unsigned Bs[32][136];

    const int tid  = threadIdx.x;
    const int warp = tid >> 5, lane = tid & 31;
    const int g    = lane >> 2, t = lane & 3;
    const int wm   = (warp >> 2) * 64;
    const int wn   = (warp & 3) * 32;
    const int row0 = blockIdx.y * 128, col0 = blockIdx.x * 128;

    const int a_m  = tid >> 3;
    const int a_k4 = (tid & 7) * 4;
    const int b_k  = tid >> 5;
    const int b_n4 = (tid & 31) * 4;

    float acc[4][4][4];
#pragma unroll
    for (int mi = 0; mi < 4; mi++)
#pragma unroll
        for (int ni = 0; ni < 4; ni++)
#pragma unroll
            for (int r = 0; r < 4; r++) acc[mi][ni][r] = 0.f;

    const float* Ap = A + (size_t)(row0 + a_m) * K + a_k4;
    const float* Wp = W + (size_t)b_k * GG + col0 + b_n4;

    float4 av[4], bv[4];
#pragma unroll
    for (int i = 0; i < 4; i++) av[i] = *(const float4*)(Ap + (size_t)(i * 32) * K);
#pragma unroll
    for (int i = 0; i < 4; i++) bv[i] = *(const float4*)(Wp + (size_t)(i * 8) * GG);

    for (int k0 = 0; k0 < K; k0 += 32) {
        __syncthreads();
#pragma unroll
        for (int i = 0; i < 4; i++) {
            uint4 u; u.x = f2tf(av[i].x); u.y = f2tf(av[i].y);
                     u.z = f2tf(av[i].z); u.w = f2tf(av[i].w);
            *(uint4*)&As[i * 32 + a_m][a_k4] = u;
        }
#pragma unroll
        for (int i = 0; i < 4; i++) {
            uint4 u; u.x = f2tf(bv[i].x); u.y = f2tf(bv[i].y);
                     u.z = f2tf(bv[i].z); u.w = f2tf(bv[i].w);
            *(uint4*)&Bs[i * 8 + b_k][b_n4] = u;
        }
        if (k0 + 32 < K) {
#pragma unroll
            for (int i = 0; i < 4; i++)
                av[i] = *(const float4*)(Ap + (size_t)(i * 32) * K + (k0 + 32));
#pragma unroll
            for (int i = 0; i < 4; i++)
                bv[i] = *(const float4*)(Wp + (size_t)(k0 + 32 + i * 8) * GG);
        }
        __syncthreads();

#pragma unroll
        for (int s = 0; s < 4; s++) {
            const int kk = s * 8;
            unsigned af[4][4];
#pragma unroll
            for (int mi = 0; mi < 4; mi++) {
                const int r = wm + mi * 16;
                af[mi][0] = As[r + g    ][kk + t];
                af[mi][1] = As[r + g + 8][kk + t];
                af[mi][2] = As[r + g    ][kk + t + 4];
                af[mi][3] = As[r + g + 8][kk + t + 4];
            }
            unsigned bfr[4][2];
#pragma unroll
            for (int ni = 0; ni < 4; ni++) {
                bfr[ni][0] = Bs[kk + t    ][wn + ni * 8 + g];
                bfr[ni][1] = Bs[kk + t + 4][wn + ni * 8 + g];
            }
#pragma unroll
            for (int mi = 0; mi < 4; mi++)
#pragma unroll
                for (int ni = 0; ni < 4; ni++)
                    mma_tf32(acc[mi][ni], af[mi], bfr[ni]);
        }
    }

#pragma unroll
    for (int mi = 0; mi < 4; mi++) {
        const int r0 = row0 + wm + mi * 16 + g;
#pragma unroll
        for (int ni = 0; ni < 4; ni++) {
            const int cb = col0 + wn + ni * 8 + 2 * t;
            const float b0 = bias[cb], b1 = bias[cb + 1];
            float2 v0; v0.x = acc[mi][ni][0] + b0; v0.y = acc[mi][ni][1] + b1;
            float2 v1; v1.x = acc[mi][ni][2] + b0; v1.y = acc[mi][ni][3] + b1;
            *(float2*)&C[(size_t)r0       * GG + cb] = v0;
            *(float2*)&C[(size_t)(r0 + 8) * GG + cb] = v1;
        }
    }
}

extern __shared__ unsigned dsm[];

// ---------------- layer-1 recurrence -----------------------------------------
// 128 blocks = 4 batch-groups x 32 col-groups. Block: 16 batches x 64 gate-cols.
// 8 warps K-split (64 k each). U frags in REGISTERS.
#define H1W 516
#define Z1P 80
#define SMEM_REC1 (16*H1W*4 + 8*16*Z1P*4)    // 73984

__global__ void __launch_bounds__(256, 1) k_rec1(
    const float* __restrict__ xw, const float* __restrict__ U,
    float* __restrict__ seq, unsigned* __restrict__ seqt)
{
    unsigned (*Hs)[H1W] = (unsigned(*)[H1W])dsm;
    float* zslab = (float*)(dsm + 16 * H1W);       // [8][16][Z1P]

    const int bx = blockIdx.x;
    const int bg = bx & 3, cg = bx >> 2;
    const int bbase = bg * 16, u0 = cg * 16;

    unsigned* myflag = &g_flags1[bg][cg * 8];
    const unsigned* gflags = &g_flags1[bg][0];

    const int tid  = threadIdx.x;
    const int warp = tid >> 5, lane = tid & 31;
    const int g    = lane >> 2, t = lane & 3;

    // U fragments -> registers (once)
    unsigned bfr[8][8][2];
#pragma unroll
    for (int s = 0; s < 8; s++)
#pragma unroll
        for (int ni = 0; ni < 8; ni++) {
            const int c = ni * 8 + g;
            const int gate = c >> 4, uu = c & 15;
            const size_t n = (size_t)gate * DD + u0 + uu;
            const int kg = warp * 64 + s * 8 + t;
            bfr[s][ni][0] = f2tf(U[(size_t)kg * GG + n]);
            bfr[s][ni][1] = f2tf(U[(size_t)(kg + 4) * GG + n]);
        }

    const int lt    = lane >> 3;
    const int arow  = ((lt & 1) << 3) + (lane & 7);
    const int akadd = (lt >> 1) << 2;

    const int gb = tid >> 4, guu = tid & 15;
    float c_reg = 0.f;

    // prefetch xw for step 0
    float xwv[4];
#pragma unroll
    for (int gate = 0; gate < 4; gate++)
        xwv[gate] = xw[((size_t)(bbase + gb) * TT + 0) * GG + (size_t)gate * DD + u0 + guu];

    for (int st = 0; st < TT; st++) {
        const int tout = st, tprev = st - 1;

        if (st > 0) bar_wait(gflags, (unsigned)st);

        float acc[8][4];
#pragma unroll
        for (int ni = 0; ni < 8; ni++)
#pragma unroll
            for (int r = 0; r < 4; r++) acc[ni][r] = 0.f;

        if (tprev >= 0) {
#pragma unroll
            for (int i = 0; i < 8; i++) {
                const int e = i * 256 + tid;
                const int b = e >> 7, k4 = (e & 127) << 2;
                *(uint4*)&Hs[b][k4] =
                    *(const uint4*)&seqt[((size_t)(bbase + b) * TT + tprev) * DD + k4];
            }
            __syncthreads();

#pragma unroll
            for (int s = 0; s < 8; s++) {
                const int kk = warp * 64 + s * 8;
                unsigned af[4];
                ldsm4(af[0], af[1], af[2], af[3], &Hs[arow][kk + akadd]);
#pragma unroll
                for (int ni = 0; ni < 8; ni++)
                    mma_tf32(acc[ni], af, bfr[s][ni]);
            }
        }

        {
            float* zs = zslab + warp * 16 * Z1P;
#pragma unroll
            for (int ni = 0; ni < 8; ni++) {
                const int c = ni * 8 + 2 * t;
                float2 v0; v0.x = acc[ni][0]; v0.y = acc[ni][1];
                float2 v1; v1.x = acc[ni][2]; v1.y = acc[ni][3];
                *(float2*)&zs[(size_t)g       * Z1P + c] = v0;
                *(float2*)&zs[(size_t)(g + 8) * Z1P + c] = v1;
            }
        }
        __syncthreads();

        {
            float z[4];
#pragma unroll
            for (int gate = 0; gate < 4; gate++) {
                const int cidx = gate * 16 + guu;
                float s = 0.f;
#pragma unroll
                for (int w = 0; w < 8; w++)
                    s += zslab[((size_t)w * 16 + gb) * Z1P + cidx];
                z[gate] = s + xwv[gate];
            }
            const float si = sigm(z[0]), sf = sigm(z[1]), so = sigm(z[3]);
            const float gr = fmaxf(z[2], 0.f);
            const float cn = sf * c_reg + si * gr;
            c_reg = cn;
            const float hv = so * fmaxf(cn, 0.f);
            const size_t idx = ((size_t)(bbase + gb) * TT + tout) * DD + u0 + guu;
            seq [idx] = hv;
            seqt[idx] = f2tf(hv);
        }

        // prefetch xw for next step (issues before the signal / next wait)
        if (st + 1 < TT) {
#pragma unroll
            for (int gate = 0; gate < 4; gate++)
                xwv[gate] = xw[((size_t)(bbase + gb) * TT + (st + 1)) * GG
                               + (size_t)gate * DD + u0 + guu];
        }

        if (st < TT - 1) bar_signal(myflag, (unsigned)(st + 1));
    }
}

// ---------------- layer-2 fused fwd/bwd recurrence ---------------------------
// 128 blocks: dir(2) x bg(2) x cg(32). Block: 32 batches x 64 gate-cols.
// U slice in SMEM n-major; B frags via ldmatrix. zslab ALIASES Hs.
#define USW 516
#define Z2P 72
#define SMEM_REC2 (64*USW*4 + 8*32*Z2P*4)    // 205824

__global__ void __launch_bounds__(256, 1) k_rec2(
    const float* __restrict__ xwf, const float* __restrict__ Uf,
    float* __restrict__ hf, unsigned* __restrict__ hft,
    const float* __restrict__ xwb, const float* __restrict__ Ub,
    float* __restrict__ hb, unsigned* __restrict__ hbt)
{
    unsigned (*Us)[USW] = (unsigned(*)[USW])dsm;
    unsigned* shreg = dsm + 64 * USW;
    unsigned (*Hs)[USW] = (unsigned(*)[USW])shreg;   // [32][516]
    float* zslab = (float*)shreg;                    // [8][32][Z2P] (alias)

    const int bx  = blockIdx.x;
    const int dir = bx >> 6;
    const int bg2 = (bx >> 5) & 1, cg = bx & 31;
    const int grp = dir * 2 + bg2;
    const int bbase = bg2 * 32, u0 = cg * 16;

    unsigned* myflag = &g_flags2[grp][cg * 8];
    const unsigned* gflags = &g_flags2[grp][0];

    const float* xw = dir ? xwb : xwf;
    const float* U  = dir ? Ub  : Uf;
    float*    seq   = dir ? hb  : hf;
    unsigned* seqt  = dir ? hbt : hft;

    const int tid  = threadIdx.x;
    const int warp = tid >> 5, lane = tid & 31;
    const int g    = lane >> 2, t = lane & 3;

    for (int idx = tid; idx < 64 * 512; idx += 256) {
        const int col = idx >> 9, k = idx & 511;
        const int gate = col >> 4, uu = col & 15;
        Us[col][k] = f2tf(U[(size_t)k * GG + (size_t)gate * DD + u0 + uu]);
    }
    __syncthreads();

    const int lt    = lane >> 3;
    const int arow  = ((lt & 1) << 3) + (lane & 7);
    const int akadd = (lt >> 1) << 2;
    const int brow  = ((lt >> 1) << 3) + (lane & 7);
    const int bkadd = (lt & 1) << 2;

    const int gbb = tid >> 3, guu = tid & 7;
    float creg[2] = {0.f, 0.f};

    // prefetch xw for step 0
    float xwv[8];
    {
        const int tout0 = dir ? (TT - 1) : 0;
        const size_t xrow = ((size_t)(bbase + gbb) * TT + tout0) * GG;
#pragma unroll
        for (int ui = 0; ui < 2; ui++)
#pragma unroll
            for (int gate = 0; gate < 4; gate++)
                xwv[ui * 4 + gate] = xw[xrow + (size_t)gate * DD + u0 + guu + ui * 8];
    }

    for (int st = 0; st < TT; st++) {
        const int tout  = dir ? (TT - 1 - st) : st;
        const int tprev = (st == 0) ? -1 : (dir ? tout + 1 : tout - 1);

        if (st > 0) bar_wait(gflags, (unsigned)st);

        float acc[2][8][4];
#pragma unroll
        for (int mi = 0; mi < 2; mi++)
#pragma unroll
            for (int ni = 0; ni < 8; ni++)
#pragma unroll
                for (int r = 0; r < 4; r++) acc[mi][ni][r] = 0.f;

        if (tprev >= 0) {
#pragma unroll
            for (int i = 0; i < 16; i++) {
                const int e = i * 256 + tid;
                const int b = e >> 7, k4 = (e & 127) << 2;
                *(uint4*)&Hs[b][k4] =
                    *(const uint4*)&seqt[((size_t)(bbase + b) * TT + tprev) * DD + k4];
            }
            __syncthreads();

#pragma unroll
            for (int s = 0; s < 8; s++) {
                const int kk = warp * 64 + s * 8;
                unsigned af[2][4];
#pragma unroll
                for (int mi = 0; mi < 2; mi++)
                    ldsm4(af[mi][0], af[mi][1], af[mi][2], af[mi][3],
                          &Hs[mi * 16 + arow][kk + akadd]);
                unsigned bfr[8][2];
#pragma unroll
                for (int np = 0; np < 4; np++) {
                    unsigned r0, r1, r2, r3;
                    ldsm4(r0, r1, r2, r3, &Us[np * 16 + brow][kk + bkadd]);
                    bfr[np * 2][0]     = r0; bfr[np * 2][1]     = r1;
                    bfr[np * 2 + 1][0] = r2; bfr[np * 2 + 1][1] = r3;
                }
#pragma unroll
                for (int mi = 0; mi < 2; mi++)
#pragma unroll
                    for (int ni = 0; ni < 8; ni++)
                        mma_tf32(acc[mi][ni], af[mi], bfr[ni]);
            }
            __syncthreads();   // all warps done reading Hs before zslab aliases
        }

        {
            float* zs = zslab + warp * 32 * Z2P;
#pragma unroll
            for (int mi = 0; mi < 2; mi++)
#pragma unroll
                for (int ni = 0; ni < 8; ni++) {
                    const int r = mi * 16, c = ni * 8 + 2 * t;
                    float2 v0; v0.x = acc[mi][ni][0]; v0.y = acc[mi][ni][1];
                    float2 v1; v1.x = acc[mi][ni][2]; v1.y = acc[mi][ni][3];
                    *(float2*)&zs[(size_t)(r + g)     * Z2P + c] = v0;
                    *(float2*)&zs[(size_t)(r + g + 8) * Z2P + c] = v1;
                }
        }
        __syncthreads();

#pragma unroll
        for (int ui = 0; ui < 2; ui++) {
            const int unit = guu + ui * 8;
            float z[4];
#pragma unroll
            for (int gate = 0; gate < 4; gate++) {
                const int cidx = gate * 16 + unit;
                float s = 0.f;
#pragma unroll
                for (int w = 0; w < 8; w++)
                    s += zslab[((size_t)w * 32 + gbb) * Z2P + cidx];
                z[gate] = s + xwv[ui * 4 + gate];
            }
            const float si = sigm(z[0]), sf = sigm(z[1]), so = sigm(z[3]);
            const float gr = fmaxf(z[2], 0.f);
            const float cn = sf * creg[ui] + si * gr;
            creg[ui] = cn;
            const float hv = so * fmaxf(cn, 0.f);
            const size_t idx = ((size_t)(bbase + gbb) * TT + tout) * DD + u0 + unit;
            seq [idx] = hv;
            seqt[idx] = f2tf(hv);
        }

        // prefetch xw for next step before signaling
        if (st + 1 < TT) {
            const int tnext = dir ? (TT - 2 - st) : (st + 1);
            const size_t xrow = ((size_t)(bbase + gbb) * TT + tnext) * GG;
#pragma unroll
            for (int ui = 0; ui < 2; ui++)
#pragma unroll
                for (int gate = 0; gate < 4; gate++)
                    xwv[ui * 4 + gate] = xw[xrow + (size_t)gate * DD + u0 + guu + ui * 8];
        }

        if (st < TT - 1) bar_signal(myflag, (unsigned)(st + 1));
    }
}

// ---------------- LayerNorm(concat(hf,hb)) * gamma + beta + residual --------
__global__ void __launch_bounds__(256) k_ln_residual(
    const float* __restrict__ x, const float* __restrict__ gamma,
    const float* __restrict__ beta, const float* __restrict__ hf,
    const float* __restrict__ hb, float* __restrict__ out)
{
    const int bt  = blockIdx.x;
    const int tid = threadIdx.x;
    const float* hfr = hf + (size_t)bt * DD;
    const float* hbr = hb + (size_t)bt * DD;

    float v[4];
    float s = 0.f;
#pragma unroll
    for (int r = 0; r < 4; r++) {
        int i = tid + r * 256;
        float val = (i < DD) ? hfr[i] : hbr[i - DD];
        v[r] = val; s += val;
    }

    __shared__ float rbuf[8];
    __shared__ float stat[2];
    const int lane = tid & 31, w = tid >> 5;
#pragma unroll
    for (int o = 16; o; o >>= 1) s += __shfl_xor_sync(0xffffffffu, s, o);
    if (lane == 0) rbuf[w] = s;
    __syncthreads();
    if (tid == 0) {
        float tsum = 0.f;
        for (int i = 0; i < 8; i++) tsum += rbuf[i];
        stat[0] = tsum * (1.f / 1024.f);
    }
    __syncthreads();
    const float mean = stat[0];

    float s2 = 0.f;
#pragma unroll
    for (int r = 0; r < 4; r++) { float d = v[r] - mean; s2 += d * d; }
#pragma unroll
    for (int o = 16; o; o >>= 1) s2 += __shfl_xor_sync(0xffffffffu, s2, o);
    if (lane == 0) rbuf[w] = s2;
    __syncthreads();
    if (tid == 0) {
        float tsum = 0.f;
        for (int i = 0; i < 8; i++) tsum += rbuf[i];
        stat[1] = rsqrtf(tsum * (1.f / 1024.f) + 1e-6f);
    }
    __syncthreads();
    const float rstd = stat[1];

    const float* xr  = x   + (size_t)bt * II;
    float*       otr = out + (size_t)bt * II;
#pragma unroll
    for (int r = 0; r < 4; r++) {
        int i = tid + r * 256;
        otr[i] = xr[i] + (v[r] - mean) * rstd * gamma[i] + beta[i];
    }
}

// ---------------- launcher ---------------------------------------------------
extern "C" void kernel_launch(void* const* d_in, const int* in_sizes, int n_in,
                              void* d_out, int out_size)
{
    (void)in_sizes; (void)n_in; (void)out_size;
    const float* x     = (const float*)d_in[0];
    const float* W1    = (const float*)d_in[1];
    const float* U1    = (const float*)d_in[2];
    const float* b1    = (const float*)d_in[3];
    const float* Wf    = (const float*)d_in[4];
    const float* Uf    = (const float*)d_in[5];
    const float* bf    = (const float*)d_in[6];
    const float* Wb    = (const float*)d_in[7];
    const float* Ub    = (const float*)d_in[8];
    const float* bb    = (const float*)d_in[9];
    const float* gamma = (const float*)d_in[10];
    const float* beta  = (const float*)d_in[11];
    float* out = (float*)d_out;

    float *xw1, *xwf, *xwb, *h1, *hf, *hb;
    unsigned *h1t, *hft, *hbt;
    cudaGetSymbolAddress((void**)&xw1, g_xw1);
    cudaGetSymbolAddress((void**)&xwf, g_xwf);
    cudaGetSymbolAddress((void**)&xwb, g_xwb);
    cudaGetSymbolAddress((void**)&h1,  g_h1);
    cudaGetSymbolAddress((void**)&hf,  g_hf);
    cudaGetSymbolAddress((void**)&hb,  g_hb);
    cudaGetSymbolAddress((void**)&h1t, g_h1t);
    cudaGetSymbolAddress((void**)&hft, g_hft);
    cudaGetSymbolAddress((void**)&hbt, g_hbt);

    cudaFuncSetAttribute(k_rec1, cudaFuncAttributeMaxDynamicSharedMemorySize, SMEM_REC1);
    cudaFuncSetAttribute(k_rec2, cudaFuncAttributeMaxDynamicSharedMemorySize, SMEM_REC2);

    dim3 ggrid(GG / 128, BT / 128);   // (16, 256)

    k_zero_flags<<<4, 256>>>();
    k_mma_gemm<<<ggrid, 256>>>(x, W1, b1, xw1, II);
    k_rec1<<<128, 256, SMEM_REC1>>>(xw1, U1, h1, h1t);
    k_mma_gemm<<<ggrid, 256>>>(h1, Wf, bf, xwf, DD);
    k_mma_gemm<<<ggrid, 256>>>(h1, Wb, bb, xwb, DD);
    k_rec2<<<128, 256, SMEM_REC2>>>(xwf, Uf, hf, hft, xwb, Ub, hb, hbt);
    k_ln_residual<<<BT, 256>>>(x, gamma, beta, hf, hb, out);
}